// round 1
// baseline (speedup 1.0000x reference)
#include <cuda_runtime.h>
#include <math_constants.h>

#define BT     8        // b*t
#define NSRC   8192
#define NLTN   64
#define NCTX   8256     // NSRC + NLTN
#define DIM    768
#define DEMB   512
#define HEADS  8
#define DHEAD  64
#define NSPLIT 16
#define NTILES 258      // NCTX / 32
#define EPS    1e-5f

// ---- scratch (device globals: no allocation allowed) ----
__device__ float g_ltn_n[BT * NLTN * DIM];            // 1.5 MB
__device__ float g_q[BT * NLTN * DEMB];               // 1 MB
__device__ float g_kv[BT * NCTX * 2 * DEMB];          // 270 MB  (k | v per row)
__device__ float g_stats[BT * NSRC * 2];              // mu, rstd per src row
__device__ float g_attnout[BT * NLTN * DEMB];         // 1 MB
__device__ float g_po[BT * HEADS * NSPLIT * NLTN * DHEAD]; // 16.8 MB
__device__ float g_pm[BT * HEADS * NSPLIT * NLTN];
__device__ float g_pl[BT * HEADS * NSPLIT * NLTN];

// ---------------- LayerNorm of ltn (512 rows) ----------------
__global__ void ln_ltn_kernel(const float* __restrict__ ltn,
                              const float* __restrict__ g,
                              const float* __restrict__ b) {
    int row = blockIdx.x;                      // 0..511
    const float* x = ltn + (size_t)row * DIM;
    int tid = threadIdx.x;
    float v0 = x[tid], v1 = x[tid + 256], v2 = x[tid + 512];
    float s  = v0 + v1 + v2;
    float s2 = v0 * v0 + v1 * v1 + v2 * v2;
    __shared__ float red[2][8];
    #pragma unroll
    for (int o = 16; o; o >>= 1) {
        s  += __shfl_xor_sync(~0u, s,  o);
        s2 += __shfl_xor_sync(~0u, s2, o);
    }
    int w = tid >> 5, l = tid & 31;
    if (l == 0) { red[0][w] = s; red[1][w] = s2; }
    __syncthreads();
    s = 0.f; s2 = 0.f;
    #pragma unroll
    for (int i = 0; i < 8; i++) { s += red[0][i]; s2 += red[1][i]; }
    float mean = s * (1.f / DIM);
    float var  = s2 * (1.f / DIM) - mean * mean;
    float rstd = rsqrtf(var + EPS);
    float* out = g_ltn_n + (size_t)row * DIM;
    out[tid]       = (v0 - mean) * rstd * g[tid]       + b[tid];
    out[tid + 256] = (v1 - mean) * rstd * g[tid + 256] + b[tid + 256];
    out[tid + 512] = (v2 - mean) * rstd * g[tid + 512] + b[tid + 512];
}

// ---------------- per-row LN stats for src (65536 rows) ----------------
__global__ void src_stats_kernel(const float* __restrict__ src) {
    int w = threadIdx.x >> 5, l = threadIdx.x & 31;
    int row = blockIdx.x * 8 + w;
    const float* x = src + (size_t)row * DIM;
    float s = 0.f, s2 = 0.f;
    #pragma unroll
    for (int i = l; i < DIM; i += 32) { float v = x[i]; s += v; s2 += v * v; }
    #pragma unroll
    for (int o = 16; o; o >>= 1) {
        s  += __shfl_xor_sync(~0u, s,  o);
        s2 += __shfl_xor_sync(~0u, s2, o);
    }
    if (l == 0) {
        float mean = s * (1.f / DIM);
        float var  = s2 * (1.f / DIM) - mean * mean;
        g_stats[row * 2]     = mean;
        g_stats[row * 2 + 1] = rsqrtf(var + EPS);
    }
}

// ---------------- classic 128x128x8 SGEMM, optional fused LN on A ----------------
// C[crow, n] = sum_k A_eff[grow, k] * W[k, n]
// crow = (grow / rows_per_bt) * out_stride + out_off + (grow % rows_per_bt)
template <bool LN>
__global__ void __launch_bounds__(256)
sgemm128(const float* __restrict__ A, const float* __restrict__ W,
         float* __restrict__ C, const float* __restrict__ stats,
         const float* __restrict__ gamma, const float* __restrict__ beta,
         int K, int N, int rows_per_bt, int out_off, int out_stride) {
    __shared__ float As[8][128];
    __shared__ float Bs[8][128];
    __shared__ float sG[LN ? DIM : 1];
    __shared__ float sB[LN ? DIM : 1];

    int tid = threadIdx.x;
    if (LN) {
        for (int i = tid; i < DIM; i += 256) { sG[i] = gamma[i]; sB[i] = beta[i]; }
        __syncthreads();
    }
    int row0 = blockIdx.y * 128, col0 = blockIdx.x * 128;

    int aRow = tid >> 1, aCol = (tid & 1) * 4;
    int bRow = tid >> 5, bCol = (tid & 31) * 4;
    int grow_a = row0 + aRow;
    float mu = 0.f, rstd = 1.f;
    if (LN) { mu = stats[grow_a * 2]; rstd = stats[grow_a * 2 + 1]; }
    const float* Aptr = A + (size_t)grow_a * K;

    int tx = tid & 15, ty = tid >> 4;
    float acc[8][8];
    #pragma unroll
    for (int i = 0; i < 8; i++)
        #pragma unroll
        for (int j = 0; j < 8; j++) acc[i][j] = 0.f;

    for (int k0 = 0; k0 < K; k0 += 8) {
        float4 av = *(const float4*)(Aptr + k0 + aCol);
        if (LN) {
            av.x = (av.x - mu) * rstd * sG[k0 + aCol + 0] + sB[k0 + aCol + 0];
            av.y = (av.y - mu) * rstd * sG[k0 + aCol + 1] + sB[k0 + aCol + 1];
            av.z = (av.z - mu) * rstd * sG[k0 + aCol + 2] + sB[k0 + aCol + 2];
            av.w = (av.w - mu) * rstd * sG[k0 + aCol + 3] + sB[k0 + aCol + 3];
        }
        As[aCol + 0][aRow] = av.x;
        As[aCol + 1][aRow] = av.y;
        As[aCol + 2][aRow] = av.z;
        As[aCol + 3][aRow] = av.w;
        float4 bv = *(const float4*)(W + (size_t)(k0 + bRow) * N + col0 + bCol);
        *(float4*)&Bs[bRow][bCol] = bv;
        __syncthreads();
        #pragma unroll
        for (int kk = 0; kk < 8; kk++) {
            float ar[8], br[8];
            *(float4*)(ar)     = *(const float4*)&As[kk][ty * 8];
            *(float4*)(ar + 4) = *(const float4*)&As[kk][ty * 8 + 4];
            *(float4*)(br)     = *(const float4*)&Bs[kk][tx * 8];
            *(float4*)(br + 4) = *(const float4*)&Bs[kk][tx * 8 + 4];
            #pragma unroll
            for (int i = 0; i < 8; i++)
                #pragma unroll
                for (int j = 0; j < 8; j++) acc[i][j] = fmaf(ar[i], br[j], acc[i][j]);
        }
        __syncthreads();
    }
    #pragma unroll
    for (int i = 0; i < 8; i++) {
        int grow = row0 + ty * 8 + i;
        int bt = grow / rows_per_bt;
        int r  = grow % rows_per_bt;
        int crow = bt * out_stride + out_off + r;
        float* cp = C + (size_t)crow * N + col0 + tx * 8;
        *(float4*)cp       = make_float4(acc[i][0], acc[i][1], acc[i][2], acc[i][3]);
        *(float4*)(cp + 4) = make_float4(acc[i][4], acc[i][5], acc[i][6], acc[i][7]);
    }
}

// ---------------- flash-decoding attention, partial pass ----------------
__global__ void __launch_bounds__(256)
attn_partial(const float* __restrict__ q, const float* __restrict__ kvp) {
    int sp = blockIdx.x, h = blockIdx.y, bt = blockIdx.z;
    __shared__ float qs[NLTN][DHEAD];       // broadcast reads -> no pad needed
    __shared__ float ks[32][DHEAD + 1];
    __shared__ float vs[32][DHEAD + 1];
    int tid = threadIdx.x, lane = tid & 31, warp = tid >> 5;

    for (int i = tid; i < NLTN * DHEAD; i += 256) {
        int qi = i >> 6, d = i & 63;
        qs[qi][d] = q[((size_t)bt * NLTN + qi) * DEMB + h * DHEAD + d];
    }
    float m_i[8], l_i[8], a0[8], a1[8];
    #pragma unroll
    for (int i = 0; i < 8; i++) { m_i[i] = -CUDART_INF_F; l_i[i] = 0.f; a0[i] = 0.f; a1[i] = 0.f; }
    int d0 = lane, d1 = lane + 32;
    const float* kvbase = kvp + (size_t)bt * NCTX * (2 * DEMB);

    for (int t = sp; t < NTILES; t += NSPLIT) {
        int j0 = t * 32;
        for (int i = tid; i < 32 * DHEAD; i += 256) {
            int jj = i >> 6, d = i & 63;
            const float* row = kvbase + (size_t)(j0 + jj) * (2 * DEMB) + h * DHEAD + d;
            ks[jj][d] = row[0];
            vs[jj][d] = row[DEMB];
        }
        __syncthreads();
        #pragma unroll
        for (int i = 0; i < 8; i++) {
            int qi = warp * 8 + i;
            float s = 0.f;
            #pragma unroll
            for (int d = 0; d < DHEAD; d++) s = fmaf(qs[qi][d], ks[lane][d], s);
            s *= 0.125f;                                   // DHEAD^-0.5
            float mt = s;
            #pragma unroll
            for (int o = 16; o; o >>= 1) mt = fmaxf(mt, __shfl_xor_sync(~0u, mt, o));
            float mnew = fmaxf(m_i[i], mt);
            float fac  = __expf(m_i[i] - mnew);
            float p    = __expf(s - mnew);
            float ls = p;
            #pragma unroll
            for (int o = 16; o; o >>= 1) ls += __shfl_xor_sync(~0u, ls, o);
            l_i[i] = l_i[i] * fac + ls;
            m_i[i] = mnew;
            a0[i] *= fac; a1[i] *= fac;
            #pragma unroll
            for (int jj = 0; jj < 32; jj++) {
                float pj = __shfl_sync(~0u, p, jj);
                a0[i] = fmaf(pj, vs[jj][d0], a0[i]);
                a1[i] = fmaf(pj, vs[jj][d1], a1[i]);
            }
        }
        __syncthreads();
    }
    int base = (bt * HEADS + h) * NSPLIT + sp;
    #pragma unroll
    for (int i = 0; i < 8; i++) {
        int qi = warp * 8 + i;
        if (lane == 0) {
            g_pm[base * NLTN + qi] = m_i[i];
            g_pl[base * NLTN + qi] = l_i[i];
        }
        float* op = g_po + ((size_t)base * NLTN + qi) * DHEAD;
        op[d0] = a0[i];
        op[d1] = a1[i];
    }
}

// ---------------- combine partials ----------------
__global__ void __launch_bounds__(256) attn_combine() {
    int bh = blockIdx.x;                 // bt*HEADS + h
    int bt = bh / HEADS, h = bh % HEADS;
    __shared__ float ws[NLTN][NSPLIT];
    __shared__ float linv[NLTN];
    int tid = threadIdx.x;
    if (tid < NLTN) {
        int row = tid;
        float m = -CUDART_INF_F;
        #pragma unroll
        for (int s = 0; s < NSPLIT; s++)
            m = fmaxf(m, g_pm[(bh * NSPLIT + s) * NLTN + row]);
        float L = 0.f;
        #pragma unroll
        for (int s = 0; s < NSPLIT; s++) {
            float w = __expf(g_pm[(bh * NSPLIT + s) * NLTN + row] - m);
            ws[row][s] = w;
            L += g_pl[(bh * NSPLIT + s) * NLTN + row] * w;
        }
        linv[row] = 1.f / L;
    }
    __syncthreads();
    for (int i = tid; i < NLTN * DHEAD; i += 256) {
        int row = i >> 6, d = i & 63;
        float acc = 0.f;
        #pragma unroll
        for (int s = 0; s < NSPLIT; s++)
            acc += g_po[(((size_t)bh * NSPLIT + s) * NLTN + row) * DHEAD + d] * ws[row][s];
        g_attnout[((size_t)bt * NLTN + row) * DEMB + h * DHEAD + d] = acc * linv[row];
    }
}

extern "C" void kernel_launch(void* const* d_in, const int* in_sizes, int n_in,
                              void* d_out, int out_size) {
    const float* src   = (const float*)d_in[0];
    const float* ltn   = (const float*)d_in[1];
    const float* gsrc  = (const float*)d_in[2];
    const float* bsrc  = (const float*)d_in[3];
    const float* gltn  = (const float*)d_in[4];
    const float* bltn  = (const float*)d_in[5];
    const float* Wq    = (const float*)d_in[6];
    const float* Wkv   = (const float*)d_in[7];
    const float* Wo    = (const float*)d_in[8];
    float* out = (float*)d_out;

    float *p_ltn_n, *p_q, *p_kv, *p_stats, *p_attn;
    cudaGetSymbolAddress((void**)&p_ltn_n, g_ltn_n);
    cudaGetSymbolAddress((void**)&p_q,     g_q);
    cudaGetSymbolAddress((void**)&p_kv,    g_kv);
    cudaGetSymbolAddress((void**)&p_stats, g_stats);
    cudaGetSymbolAddress((void**)&p_attn,  g_attnout);

    // 1) LN(ltn) and src row stats
    ln_ltn_kernel<<<BT * NLTN, 256>>>(ltn, gltn, bltn);
    src_stats_kernel<<<BT * NSRC / 8, 256>>>(src);

    // 2) q = ltn_n @ Wq   [512 x 512], crow == grow
    sgemm128<false><<<dim3(DEMB / 128, (BT * NLTN) / 128), 256>>>(
        p_ltn_n, Wq, p_q, nullptr, nullptr, nullptr,
        DIM, DEMB, BT * NLTN, 0, 0);

    // 3) kv (src rows, fused LN): [65536 x 1024]
    sgemm128<true><<<dim3(1024 / 128, (BT * NSRC) / 128), 256>>>(
        src, Wkv, p_kv, p_stats, gsrc, bsrc,
        DIM, 2 * DEMB, NSRC, 0, NCTX);

    // 4) kv (ltn rows): [512 x 1024] appended at row 8192 of each bt chunk
    sgemm128<false><<<dim3(1024 / 128, (BT * NLTN) / 128), 256>>>(
        p_ltn_n, Wkv, p_kv, nullptr, nullptr, nullptr,
        DIM, 2 * DEMB, NLTN, NSRC, NCTX);

    // 5) attention (split-KV flash decoding) + combine
    attn_partial<<<dim3(NSPLIT, HEADS, BT), 256>>>(p_q, p_kv);
    attn_combine<<<BT * HEADS, 256>>>();

    // 6) out = attn_out @ Wo   [512 x 768]
    sgemm128<false><<<dim3(DIM / 128, (BT * NLTN) / 128), 256>>>(
        p_attn, Wo, out, nullptr, nullptr, nullptr,
        DEMB, DIM, BT * NLTN, 0, 0);
}

// round 2
// speedup vs baseline: 1.9804x; 1.9804x over previous
#include <cuda_runtime.h>
#include <math_constants.h>
#include <cstdint>

#define BT     8        // b*t
#define NSRC   8192
#define NLTN   64
#define NCTX   8256     // NSRC + NLTN
#define DIM    768
#define DEMB   512
#define HEADS  8
#define DHEAD  64
#define NSPLIT 16
#define NTILES 258      // NCTX / 32
#define EPS    1e-5f

// ---- scratch (device globals: no allocation allowed) ----
__device__ float g_ltn_n[BT * NLTN * DIM];            // 1.5 MB
__device__ float g_q[BT * NLTN * DEMB];               // 1 MB
__device__ float g_kv[BT * NCTX * 2 * DEMB];          // 270 MB  (k | v per row)
__device__ float g_stats[BT * NSRC * 2];              // mu, rstd per src row
__device__ float g_attnout[BT * NLTN * DEMB];         // 1 MB
__device__ float g_po[BT * HEADS * NSPLIT * NLTN * DHEAD]; // 16.8 MB
__device__ float g_pm[BT * HEADS * NSPLIT * NLTN];
__device__ float g_pl[BT * HEADS * NSPLIT * NLTN];

// ---------------- LayerNorm of ltn (512 rows) ----------------
__global__ void ln_ltn_kernel(const float* __restrict__ ltn,
                              const float* __restrict__ g,
                              const float* __restrict__ b) {
    int row = blockIdx.x;                      // 0..511
    const float* x = ltn + (size_t)row * DIM;
    int tid = threadIdx.x;
    float v0 = x[tid], v1 = x[tid + 256], v2 = x[tid + 512];
    float s  = v0 + v1 + v2;
    float s2 = v0 * v0 + v1 * v1 + v2 * v2;
    __shared__ float red[2][8];
    #pragma unroll
    for (int o = 16; o; o >>= 1) {
        s  += __shfl_xor_sync(~0u, s,  o);
        s2 += __shfl_xor_sync(~0u, s2, o);
    }
    int w = tid >> 5, l = tid & 31;
    if (l == 0) { red[0][w] = s; red[1][w] = s2; }
    __syncthreads();
    s = 0.f; s2 = 0.f;
    #pragma unroll
    for (int i = 0; i < 8; i++) { s += red[0][i]; s2 += red[1][i]; }
    float mean = s * (1.f / DIM);
    float var  = s2 * (1.f / DIM) - mean * mean;
    float rstd = rsqrtf(var + EPS);
    float* out = g_ltn_n + (size_t)row * DIM;
    out[tid]       = (v0 - mean) * rstd * g[tid]       + b[tid];
    out[tid + 256] = (v1 - mean) * rstd * g[tid + 256] + b[tid + 256];
    out[tid + 512] = (v2 - mean) * rstd * g[tid + 512] + b[tid + 512];
}

// ---------------- per-row LN stats for src (65536 rows) ----------------
__global__ void src_stats_kernel(const float* __restrict__ src) {
    int w = threadIdx.x >> 5, l = threadIdx.x & 31;
    int row = blockIdx.x * 8 + w;
    const float* x = src + (size_t)row * DIM;
    float s = 0.f, s2 = 0.f;
    #pragma unroll
    for (int i = l; i < DIM; i += 32) { float v = x[i]; s += v; s2 += v * v; }
    #pragma unroll
    for (int o = 16; o; o >>= 1) {
        s  += __shfl_xor_sync(~0u, s,  o);
        s2 += __shfl_xor_sync(~0u, s2, o);
    }
    if (l == 0) {
        float mean = s * (1.f / DIM);
        float var  = s2 * (1.f / DIM) - mean * mean;
        g_stats[row * 2]     = mean;
        g_stats[row * 2 + 1] = rsqrtf(var + EPS);
    }
}

// ---------------- tf32 helpers ----------------
__device__ __forceinline__ uint32_t f2tf32(float f) {
    uint32_t u;
    asm("cvt.rna.tf32.f32 %0, %1;" : "=r"(u) : "f"(f));
    return u;
}

__device__ __forceinline__ void mma_tf32(float* d, const uint32_t* a, const uint32_t* b) {
    asm volatile(
        "mma.sync.aligned.m16n8k8.row.col.f32.tf32.tf32.f32 "
        "{%0,%1,%2,%3}, {%4,%5,%6,%7}, {%8,%9}, {%0,%1,%2,%3};\n"
        : "+f"(d[0]), "+f"(d[1]), "+f"(d[2]), "+f"(d[3])
        : "r"(a[0]), "r"(a[1]), "r"(a[2]), "r"(a[3]), "r"(b[0]), "r"(b[1]));
}

// ---------------- KV projection of src rows: tf32 tensor cores, fused LN ----------------
// C[bt*NCTX + r, n] = LN(A[grow,:]) @ W[:, n],  A = src [65536 x 768], W = Wkv [768 x 1024]
__global__ void __launch_bounds__(256)
kv_src_tf32(const float* __restrict__ A, const float* __restrict__ W,
            float* __restrict__ C, const float* __restrict__ stats,
            const float* __restrict__ gamma, const float* __restrict__ beta) {
    __shared__ uint32_t As[128][36];    // [m][k], pad 36 -> bank = (4r+c)%32
    __shared__ uint32_t Bs[32][136];    // [k][n], pad 136 -> bank = (8r+c)%32
    __shared__ float sG[DIM], sB[DIM];

    const int tid = threadIdx.x;
    const int lane = tid & 31, warp = tid >> 5;
    const int row0 = blockIdx.y * 128, col0 = blockIdx.x * 128;
    const int bt  = row0 / NSRC;
    const int rin = row0 % NSRC;
    const int N   = 2 * DEMB;

    for (int i = tid; i < DIM; i += 256) { sG[i] = gamma[i]; sB[i] = beta[i]; }

    // A-load assignment: 4 slots per thread, each slot = one float4 along k
    int arow[4]; float amu[4], ars[4];
    #pragma unroll
    for (int i = 0; i < 4; i++) {
        int slot = tid + i * 256;
        arow[i] = slot >> 3;
        int grow = row0 + arow[i];
        amu[i] = stats[grow * 2];
        ars[i] = stats[grow * 2 + 1];
    }
    const int akc = (tid & 7) * 4;

    const int wm = warp & 3, wn = warp >> 2;
    const int m0w = wm * 32, n0w = wn * 64;
    const int g = lane >> 2, t = lane & 3;

    float acc[2][8][4];
    #pragma unroll
    for (int mt = 0; mt < 2; mt++)
        #pragma unroll
        for (int nt = 0; nt < 8; nt++)
            #pragma unroll
            for (int e = 0; e < 4; e++) acc[mt][nt][e] = 0.f;

    __syncthreads();   // sG/sB ready

    for (int k0 = 0; k0 < DIM; k0 += 32) {
        // stage A tile (LN fused) -> As
        #pragma unroll
        for (int i = 0; i < 4; i++) {
            const float4 av = *(const float4*)(A + (size_t)(row0 + arow[i]) * DIM + k0 + akc);
            uint4 u;
            u.x = f2tf32((av.x - amu[i]) * ars[i] * sG[k0 + akc + 0] + sB[k0 + akc + 0]);
            u.y = f2tf32((av.y - amu[i]) * ars[i] * sG[k0 + akc + 1] + sB[k0 + akc + 1]);
            u.z = f2tf32((av.z - amu[i]) * ars[i] * sG[k0 + akc + 2] + sB[k0 + akc + 2]);
            u.w = f2tf32((av.w - amu[i]) * ars[i] * sG[k0 + akc + 3] + sB[k0 + akc + 3]);
            *(uint4*)&As[arow[i]][akc] = u;
        }
        // stage B tile -> Bs
        #pragma unroll
        for (int i = 0; i < 4; i++) {
            int krow = warp + i * 8;
            int nc = lane * 4;
            const float4 bv = *(const float4*)(W + (size_t)(k0 + krow) * N + col0 + nc);
            uint4 u;
            u.x = f2tf32(bv.x); u.y = f2tf32(bv.y); u.z = f2tf32(bv.z); u.w = f2tf32(bv.w);
            *(uint4*)&Bs[krow][nc] = u;
        }
        __syncthreads();
        #pragma unroll
        for (int ks = 0; ks < 4; ks++) {
            const int k8 = ks * 8;
            uint32_t af[2][4], bf[8][2];
            #pragma unroll
            for (int mt = 0; mt < 2; mt++) {
                int r = m0w + mt * 16 + g;
                af[mt][0] = As[r][k8 + t];
                af[mt][1] = As[r + 8][k8 + t];
                af[mt][2] = As[r][k8 + t + 4];
                af[mt][3] = As[r + 8][k8 + t + 4];
            }
            #pragma unroll
            for (int nt = 0; nt < 8; nt++) {
                int c = n0w + nt * 8 + g;
                bf[nt][0] = Bs[k8 + t][c];
                bf[nt][1] = Bs[k8 + 4 + t][c];
            }
            #pragma unroll
            for (int nt = 0; nt < 8; nt++)
                #pragma unroll
                for (int mt = 0; mt < 2; mt++)
                    mma_tf32(acc[mt][nt], af[mt], bf[nt]);
        }
        __syncthreads();
    }

    // epilogue: d0,d1 -> (row, 2t..2t+1); d2,d3 -> (row+8, ...)
    const size_t crow0 = (size_t)bt * NCTX + rin;
    #pragma unroll
    for (int mt = 0; mt < 2; mt++) {
        int r = m0w + mt * 16 + g;
        float* c0 = C + (crow0 + row0 % 1 /*0*/ + r) * (size_t)N + col0 + n0w + 2 * t;
        float* c1 = c0 + 8 * (size_t)N;
        #pragma unroll
        for (int nt = 0; nt < 8; nt++) {
            *(float2*)(c0 + nt * 8) = make_float2(acc[mt][nt][0], acc[mt][nt][1]);
            *(float2*)(c1 + nt * 8) = make_float2(acc[mt][nt][2], acc[mt][nt][3]);
        }
    }
}

// ---------------- classic 128x128x8 SGEMM (fp32, exact) ----------------
// C[crow, n] = sum_k A[grow, k] * W[k, n]
// crow = (grow / rows_per_bt) * out_stride + out_off + (grow % rows_per_bt)
__global__ void __launch_bounds__(256)
sgemm128(const float* __restrict__ A, const float* __restrict__ W,
         float* __restrict__ C,
         int K, int N, int rows_per_bt, int out_off, int out_stride) {
    __shared__ float As[8][128];
    __shared__ float Bs[8][128];

    int tid = threadIdx.x;
    int row0 = blockIdx.y * 128, col0 = blockIdx.x * 128;

    int aRow = tid >> 1, aCol = (tid & 1) * 4;
    int bRow = tid >> 5, bCol = (tid & 31) * 4;
    const float* Aptr = A + (size_t)(row0 + aRow) * K;

    int tx = tid & 15, ty = tid >> 4;
    float acc[8][8];
    #pragma unroll
    for (int i = 0; i < 8; i++)
        #pragma unroll
        for (int j = 0; j < 8; j++) acc[i][j] = 0.f;

    for (int k0 = 0; k0 < K; k0 += 8) {
        float4 av = *(const float4*)(Aptr + k0 + aCol);
        As[aCol + 0][aRow] = av.x;
        As[aCol + 1][aRow] = av.y;
        As[aCol + 2][aRow] = av.z;
        As[aCol + 3][aRow] = av.w;
        float4 bv = *(const float4*)(W + (size_t)(k0 + bRow) * N + col0 + bCol);
        *(float4*)&Bs[bRow][bCol] = bv;
        __syncthreads();
        #pragma unroll
        for (int kk = 0; kk < 8; kk++) {
            float ar[8], br[8];
            *(float4*)(ar)     = *(const float4*)&As[kk][ty * 8];
            *(float4*)(ar + 4) = *(const float4*)&As[kk][ty * 8 + 4];
            *(float4*)(br)     = *(const float4*)&Bs[kk][tx * 8];
            *(float4*)(br + 4) = *(const float4*)&Bs[kk][tx * 8 + 4];
            #pragma unroll
            for (int i = 0; i < 8; i++)
                #pragma unroll
                for (int j = 0; j < 8; j++) acc[i][j] = fmaf(ar[i], br[j], acc[i][j]);
        }
        __syncthreads();
    }
    #pragma unroll
    for (int i = 0; i < 8; i++) {
        int grow = row0 + ty * 8 + i;
        int bt = grow / rows_per_bt;
        int r  = grow % rows_per_bt;
        int crow = bt * out_stride + out_off + r;
        float* cp = C + (size_t)crow * N + col0 + tx * 8;
        *(float4*)cp       = make_float4(acc[i][0], acc[i][1], acc[i][2], acc[i][3]);
        *(float4*)(cp + 4) = make_float4(acc[i][4], acc[i][5], acc[i][6], acc[i][7]);
    }
}

// ---------------- flash-decoding attention, partial pass ----------------
__global__ void __launch_bounds__(256)
attn_partial(const float* __restrict__ q, const float* __restrict__ kvp) {
    int sp = blockIdx.x, h = blockIdx.y, bt = blockIdx.z;
    __shared__ float qs[NLTN][DHEAD];       // broadcast reads -> no pad needed
    __shared__ float ks[32][DHEAD + 1];
    __shared__ float vs[32][DHEAD + 1];
    int tid = threadIdx.x, lane = tid & 31, warp = tid >> 5;

    for (int i = tid; i < NLTN * DHEAD; i += 256) {
        int qi = i >> 6, d = i & 63;
        qs[qi][d] = q[((size_t)bt * NLTN + qi) * DEMB + h * DHEAD + d];
    }
    float m_i[8], l_i[8], a0[8], a1[8];
    #pragma unroll
    for (int i = 0; i < 8; i++) { m_i[i] = -CUDART_INF_F; l_i[i] = 0.f; a0[i] = 0.f; a1[i] = 0.f; }
    int d0 = lane, d1 = lane + 32;
    const float* kvbase = kvp + (size_t)bt * NCTX * (2 * DEMB);

    for (int t = sp; t < NTILES; t += NSPLIT) {
        int j0 = t * 32;
        for (int i = tid; i < 32 * DHEAD; i += 256) {
            int jj = i >> 6, d = i & 63;
            const float* row = kvbase + (size_t)(j0 + jj) * (2 * DEMB) + h * DHEAD + d;
            ks[jj][d] = row[0];
            vs[jj][d] = row[DEMB];
        }
        __syncthreads();
        #pragma unroll
        for (int i = 0; i < 8; i++) {
            int qi = warp * 8 + i;
            float s = 0.f;
            #pragma unroll
            for (int d = 0; d < DHEAD; d++) s = fmaf(qs[qi][d], ks[lane][d], s);
            s *= 0.125f;                                   // DHEAD^-0.5
            float mt = s;
            #pragma unroll
            for (int o = 16; o; o >>= 1) mt = fmaxf(mt, __shfl_xor_sync(~0u, mt, o));
            float mnew = fmaxf(m_i[i], mt);
            float fac  = __expf(m_i[i] - mnew);
            float p    = __expf(s - mnew);
            float ls = p;
            #pragma unroll
            for (int o = 16; o; o >>= 1) ls += __shfl_xor_sync(~0u, ls, o);
            l_i[i] = l_i[i] * fac + ls;
            m_i[i] = mnew;
            a0[i] *= fac; a1[i] *= fac;
            #pragma unroll
            for (int jj = 0; jj < 32; jj++) {
                float pj = __shfl_sync(~0u, p, jj);
                a0[i] = fmaf(pj, vs[jj][d0], a0[i]);
                a1[i] = fmaf(pj, vs[jj][d1], a1[i]);
            }
        }
        __syncthreads();
    }
    int base = (bt * HEADS + h) * NSPLIT + sp;
    #pragma unroll
    for (int i = 0; i < 8; i++) {
        int qi = warp * 8 + i;
        if (lane == 0) {
            g_pm[base * NLTN + qi] = m_i[i];
            g_pl[base * NLTN + qi] = l_i[i];
        }
        float* op = g_po + ((size_t)base * NLTN + qi) * DHEAD;
        op[d0] = a0[i];
        op[d1] = a1[i];
    }
}

// ---------------- combine partials ----------------
__global__ void __launch_bounds__(256) attn_combine() {
    int bh = blockIdx.x;                 // bt*HEADS + h
    int bt = bh / HEADS, h = bh % HEADS;
    __shared__ float ws[NLTN][NSPLIT];
    __shared__ float linv[NLTN];
    int tid = threadIdx.x;
    if (tid < NLTN) {
        int row = tid;
        float m = -CUDART_INF_F;
        #pragma unroll
        for (int s = 0; s < NSPLIT; s++)
            m = fmaxf(m, g_pm[(bh * NSPLIT + s) * NLTN + row]);
        float L = 0.f;
        #pragma unroll
        for (int s = 0; s < NSPLIT; s++) {
            float w = __expf(g_pm[(bh * NSPLIT + s) * NLTN + row] - m);
            ws[row][s] = w;
            L += g_pl[(bh * NSPLIT + s) * NLTN + row] * w;
        }
        linv[row] = 1.f / L;
    }
    __syncthreads();
    for (int i = tid; i < NLTN * DHEAD; i += 256) {
        int row = i >> 6, d = i & 63;
        float acc = 0.f;
        #pragma unroll
        for (int s = 0; s < NSPLIT; s++)
            acc += g_po[(((size_t)bh * NSPLIT + s) * NLTN + row) * DHEAD + d] * ws[row][s];
        g_attnout[((size_t)bt * NLTN + row) * DEMB + h * DHEAD + d] = acc * linv[row];
    }
}

extern "C" void kernel_launch(void* const* d_in, const int* in_sizes, int n_in,
                              void* d_out, int out_size) {
    const float* src   = (const float*)d_in[0];
    const float* ltn   = (const float*)d_in[1];
    const float* gsrc  = (const float*)d_in[2];
    const float* bsrc  = (const float*)d_in[3];
    const float* gltn  = (const float*)d_in[4];
    const float* bltn  = (const float*)d_in[5];
    const float* Wq    = (const float*)d_in[6];
    const float* Wkv   = (const float*)d_in[7];
    const float* Wo    = (const float*)d_in[8];
    float* out = (float*)d_out;

    float *p_ltn_n, *p_q, *p_kv, *p_stats, *p_attn;
    cudaGetSymbolAddress((void**)&p_ltn_n, g_ltn_n);
    cudaGetSymbolAddress((void**)&p_q,     g_q);
    cudaGetSymbolAddress((void**)&p_kv,    g_kv);
    cudaGetSymbolAddress((void**)&p_stats, g_stats);
    cudaGetSymbolAddress((void**)&p_attn,  g_attnout);

    // 1) LN(ltn) and src row stats
    ln_ltn_kernel<<<BT * NLTN, 256>>>(ltn, gltn, bltn);
    src_stats_kernel<<<BT * NSRC / 8, 256>>>(src);

    // 2) q = ltn_n @ Wq   [512 x 512] (fp32, exact)
    sgemm128<<<dim3(DEMB / 128, (BT * NLTN) / 128), 256>>>(
        p_ltn_n, Wq, p_q, DIM, DEMB, BT * NLTN, 0, 0);

    // 3) kv (src rows, fused LN): [65536 x 1024] tf32 tensor cores
    kv_src_tf32<<<dim3(1024 / 128, (BT * NSRC) / 128), 256>>>(
        src, Wkv, p_kv, p_stats, gsrc, bsrc);

    // 4) kv (ltn rows): [512 x 1024] appended at row 8192 of each bt chunk (fp32)
    sgemm128<<<dim3(1024 / 128, (BT * NLTN) / 128), 256>>>(
        p_ltn_n, Wkv, p_kv, DIM, 2 * DEMB, NLTN, NSRC, NCTX);

    // 5) attention (split-KV flash decoding) + combine
    attn_partial<<<dim3(NSPLIT, HEADS, BT), 256>>>(p_q, p_kv);
    attn_combine<<<BT * HEADS, 256>>>();

    // 6) out = attn_out @ Wo   [512 x 768] (fp32)
    sgemm128<<<dim3(DIM / 128, (BT * NLTN) / 128), 256>>>(
        p_attn, Wo, out, DEMB, DIM, BT * NLTN, 0, 0);
}

// round 3
// speedup vs baseline: 2.6484x; 1.3373x over previous
#include <cuda_runtime.h>
#include <math_constants.h>
#include <cstdint>

#define BT     8        // b*t
#define NSRC   8192
#define NLTN   64
#define NCTX   8256     // NSRC + NLTN
#define DIM    768
#define DEMB   512
#define HEADS  8
#define DHEAD  64
#define NSPLIT 16
#define KTILES 129      // NCTX / 64
#define EPS    1e-5f

// ---- scratch (device globals: no allocation allowed) ----
__device__ float g_ltn_n[BT * NLTN * DIM];
__device__ float g_q[BT * NLTN * DEMB];
__device__ float g_kv[BT * NCTX * 2 * DEMB];          // 270 MB (k | v per row)
__device__ float g_stats[BT * NSRC * 2];              // mu, rstd per src row
__device__ float g_attnout[BT * NLTN * DEMB];
__device__ float g_po[BT * HEADS * NSPLIT * NLTN * DHEAD];
__device__ float g_pm[BT * HEADS * NSPLIT * NLTN];
__device__ float g_pl[BT * HEADS * NSPLIT * NLTN];

// ---------------- LayerNorm of ltn (512 rows) ----------------
__global__ void ln_ltn_kernel(const float* __restrict__ ltn,
                              const float* __restrict__ g,
                              const float* __restrict__ b) {
    int row = blockIdx.x;
    const float* x = ltn + (size_t)row * DIM;
    int tid = threadIdx.x;
    float v0 = x[tid], v1 = x[tid + 256], v2 = x[tid + 512];
    float s  = v0 + v1 + v2;
    float s2 = v0 * v0 + v1 * v1 + v2 * v2;
    __shared__ float red[2][8];
    #pragma unroll
    for (int o = 16; o; o >>= 1) {
        s  += __shfl_xor_sync(~0u, s,  o);
        s2 += __shfl_xor_sync(~0u, s2, o);
    }
    int w = tid >> 5, l = tid & 31;
    if (l == 0) { red[0][w] = s; red[1][w] = s2; }
    __syncthreads();
    s = 0.f; s2 = 0.f;
    #pragma unroll
    for (int i = 0; i < 8; i++) { s += red[0][i]; s2 += red[1][i]; }
    float mean = s * (1.f / DIM);
    float var  = s2 * (1.f / DIM) - mean * mean;
    float rstd = rsqrtf(var + EPS);
    float* out = g_ltn_n + (size_t)row * DIM;
    out[tid]       = (v0 - mean) * rstd * g[tid]       + b[tid];
    out[tid + 256] = (v1 - mean) * rstd * g[tid + 256] + b[tid + 256];
    out[tid + 512] = (v2 - mean) * rstd * g[tid + 512] + b[tid + 512];
}

// ---------------- per-row LN stats for src ----------------
__global__ void src_stats_kernel(const float* __restrict__ src) {
    int w = threadIdx.x >> 5, l = threadIdx.x & 31;
    int row = blockIdx.x * 8 + w;
    const float* x = src + (size_t)row * DIM;
    float s = 0.f, s2 = 0.f;
    #pragma unroll
    for (int i = l; i < DIM; i += 32) { float v = x[i]; s += v; s2 += v * v; }
    #pragma unroll
    for (int o = 16; o; o >>= 1) {
        s  += __shfl_xor_sync(~0u, s,  o);
        s2 += __shfl_xor_sync(~0u, s2, o);
    }
    if (l == 0) {
        float mean = s * (1.f / DIM);
        float var  = s2 * (1.f / DIM) - mean * mean;
        g_stats[row * 2]     = mean;
        g_stats[row * 2 + 1] = rsqrtf(var + EPS);
    }
}

// ---------------- tf32 / mma / cp.async helpers ----------------
__device__ __forceinline__ uint32_t f2tf32(float f) {
    uint32_t u;
    asm("cvt.rna.tf32.f32 %0, %1;" : "=r"(u) : "f"(f));
    return u;
}
__device__ __forceinline__ void mma_tf32(float* d, const uint32_t* a, const uint32_t* b) {
    asm volatile(
        "mma.sync.aligned.m16n8k8.row.col.f32.tf32.tf32.f32 "
        "{%0,%1,%2,%3}, {%4,%5,%6,%7}, {%8,%9}, {%0,%1,%2,%3};\n"
        : "+f"(d[0]), "+f"(d[1]), "+f"(d[2]), "+f"(d[3])
        : "r"(a[0]), "r"(a[1]), "r"(a[2]), "r"(a[3]), "r"(b[0]), "r"(b[1]));
}
__device__ __forceinline__ void cp16(void* dst_smem, const void* src) {
    uint32_t d = (uint32_t)__cvta_generic_to_shared(dst_smem);
    asm volatile("cp.async.cg.shared.global [%0], [%1], 16;" :: "r"(d), "l"(src));
}
#define CP_COMMIT() asm volatile("cp.async.commit_group;")
#define CP_WAIT1()  asm volatile("cp.async.wait_group 1;")
#define CP_WAIT0()  asm volatile("cp.async.wait_group 0;")

// ---------------- KV projection (src rows): tf32, cp.async double-buffered ----------------
// dynamic smem layout (floats):
//   As[2][128][36]   raw fp32 A tiles
//   Bs[2][32][136]   raw fp32 W tiles
//   sG[768], sB[768]
#define KV_AS(b,r,c)  dyn[(b) * (128*36) + (r) * 36 + (c)]
#define KV_BS(b,r,c)  dyn[9216 + (b) * (32*136) + (r) * 136 + (c)]
#define KV_SG(i)      dyn[17920 + (i)]
#define KV_SB(i)      dyn[18688 + (i)]
#define KV_SMEM_BYTES (19456 * 4)

__global__ void __launch_bounds__(256, 2)
kv_src_tf32(const float* __restrict__ A, const float* __restrict__ W,
            float* __restrict__ C, const float* __restrict__ stats,
            const float* __restrict__ gamma, const float* __restrict__ beta) {
    extern __shared__ float dyn[];
    const int tid = threadIdx.x;
    const int lane = tid & 31, warp = tid >> 5;
    const int row0 = blockIdx.y * 128, col0 = blockIdx.x * 128;
    const int N = 2 * DEMB;

    for (int i = tid; i < DIM; i += 256) { KV_SG(i) = gamma[i]; KV_SB(i) = beta[i]; }

    const int wm = warp & 3, wn = warp >> 2;
    const int m0w = wm * 32, n0w = wn * 64;
    const int g = lane >> 2, t = lane & 3;

    // per-thread LN stats for the 4 A-rows this thread's fragments touch
    float rs[4], nmrs[4];
    #pragma unroll
    for (int i = 0; i < 4; i++) {
        int row = row0 + m0w + g + i * 8;
        float mu = stats[row * 2];
        float rv = stats[row * 2 + 1];
        rs[i] = rv; nmrs[i] = -mu * rv;
    }

    float acc[2][8][4];
    #pragma unroll
    for (int mt = 0; mt < 2; mt++)
        #pragma unroll
        for (int nt = 0; nt < 8; nt++)
            #pragma unroll
            for (int e = 0; e < 4; e++) acc[mt][nt][e] = 0.f;

    // prefetch helper (A: 128x32 chunk, B: 32x128 chunk), 4+4 cp.async.16B per thread
    auto prefetch = [&](int buf, int c) {
        int k0 = c * 32;
        #pragma unroll
        for (int i = 0; i < 4; i++) {
            int slot = tid + i * 256;
            int r = slot >> 3, c4 = (slot & 7) * 4;
            cp16(&KV_AS(buf, r, c4), A + (size_t)(row0 + r) * DIM + k0 + c4);
        }
        #pragma unroll
        for (int i = 0; i < 4; i++) {
            int slot = tid + i * 256;
            int r = slot >> 5, c4 = (slot & 31) * 4;
            cp16(&KV_BS(buf, r, c4), W + (size_t)(k0 + r) * N + col0 + c4);
        }
    };

    prefetch(0, 0);
    CP_COMMIT();

    for (int c = 0; c < 24; c++) {
        if (c < 23) { prefetch((c + 1) & 1, c + 1); CP_COMMIT(); CP_WAIT1(); }
        else        { CP_WAIT0(); }
        __syncthreads();

        const int b = c & 1;
        const int k0 = c * 32;
        #pragma unroll
        for (int ks8 = 0; ks8 < 4; ks8++) {
            const int k8 = ks8 * 8;
            float gm0 = KV_SG(k0 + k8 + t),     bt0 = KV_SB(k0 + k8 + t);
            float gm1 = KV_SG(k0 + k8 + t + 4), bt1 = KV_SB(k0 + k8 + t + 4);
            uint32_t af[2][4];
            #pragma unroll
            for (int mt = 0; mt < 2; mt++) {
                int r = m0w + mt * 16 + g;
                float a0 = KV_AS(b, r,     k8 + t);
                float a1 = KV_AS(b, r + 8, k8 + t);
                float a2 = KV_AS(b, r,     k8 + t + 4);
                float a3 = KV_AS(b, r + 8, k8 + t + 4);
                int s0 = mt * 2, s1 = mt * 2 + 1;
                af[mt][0] = f2tf32(fmaf(fmaf(a0, rs[s0], nmrs[s0]), gm0, bt0));
                af[mt][1] = f2tf32(fmaf(fmaf(a1, rs[s1], nmrs[s1]), gm0, bt0));
                af[mt][2] = f2tf32(fmaf(fmaf(a2, rs[s0], nmrs[s0]), gm1, bt1));
                af[mt][3] = f2tf32(fmaf(fmaf(a3, rs[s1], nmrs[s1]), gm1, bt1));
            }
            #pragma unroll
            for (int nt = 0; nt < 8; nt++) {
                uint32_t bf[2];
                int cc = n0w + nt * 8 + g;
                bf[0] = f2tf32(KV_BS(b, k8 + t,     cc));
                bf[1] = f2tf32(KV_BS(b, k8 + 4 + t, cc));
                mma_tf32(acc[0][nt], af[0], bf);
                mma_tf32(acc[1][nt], af[1], bf);
            }
        }
        __syncthreads();
    }

    // epilogue
    const int bt  = row0 / NSRC;
    const int rin = row0 % NSRC;
    const size_t crow0 = (size_t)bt * NCTX + rin;
    #pragma unroll
    for (int mt = 0; mt < 2; mt++) {
        int r = m0w + mt * 16 + g;
        float* c0 = C + (crow0 + r) * (size_t)N + col0 + n0w + 2 * t;
        float* c1 = c0 + 8 * (size_t)N;
        #pragma unroll
        for (int nt = 0; nt < 8; nt++) {
            *(float2*)(c0 + nt * 8) = make_float2(acc[mt][nt][0], acc[mt][nt][1]);
            *(float2*)(c1 + nt * 8) = make_float2(acc[mt][nt][2], acc[mt][nt][3]);
        }
    }
}

// ---------------- classic 128x128x8 SGEMM (fp32, exact) for small GEMMs ----------------
__global__ void __launch_bounds__(256)
sgemm128(const float* __restrict__ A, const float* __restrict__ W,
         float* __restrict__ C,
         int K, int N, int rows_per_bt, int out_off, int out_stride) {
    __shared__ float As[8][128];
    __shared__ float Bs[8][128];

    int tid = threadIdx.x;
    int row0 = blockIdx.y * 128, col0 = blockIdx.x * 128;

    int aRow = tid >> 1, aCol = (tid & 1) * 4;
    int bRow = tid >> 5, bCol = (tid & 31) * 4;
    const float* Aptr = A + (size_t)(row0 + aRow) * K;

    int tx = tid & 15, ty = tid >> 4;
    float acc[8][8];
    #pragma unroll
    for (int i = 0; i < 8; i++)
        #pragma unroll
        for (int j = 0; j < 8; j++) acc[i][j] = 0.f;

    for (int k0 = 0; k0 < K; k0 += 8) {
        float4 av = *(const float4*)(Aptr + k0 + aCol);
        As[aCol + 0][aRow] = av.x;
        As[aCol + 1][aRow] = av.y;
        As[aCol + 2][aRow] = av.z;
        As[aCol + 3][aRow] = av.w;
        float4 bv = *(const float4*)(W + (size_t)(k0 + bRow) * N + col0 + bCol);
        *(float4*)&Bs[bRow][bCol] = bv;
        __syncthreads();
        #pragma unroll
        for (int kk = 0; kk < 8; kk++) {
            float ar[8], br[8];
            *(float4*)(ar)     = *(const float4*)&As[kk][ty * 8];
            *(float4*)(ar + 4) = *(const float4*)&As[kk][ty * 8 + 4];
            *(float4*)(br)     = *(const float4*)&Bs[kk][tx * 8];
            *(float4*)(br + 4) = *(const float4*)&Bs[kk][tx * 8 + 4];
            #pragma unroll
            for (int i = 0; i < 8; i++)
                #pragma unroll
                for (int j = 0; j < 8; j++) acc[i][j] = fmaf(ar[i], br[j], acc[i][j]);
        }
        __syncthreads();
    }
    #pragma unroll
    for (int i = 0; i < 8; i++) {
        int grow = row0 + ty * 8 + i;
        int bt = grow / rows_per_bt;
        int r  = grow % rows_per_bt;
        int crow = bt * out_stride + out_off + r;
        float* cp = C + (size_t)crow * N + col0 + tx * 8;
        *(float4*)cp       = make_float4(acc[i][0], acc[i][1], acc[i][2], acc[i][3]);
        *(float4*)(cp + 4) = make_float4(acc[i][4], acc[i][5], acc[i][6], acc[i][7]);
    }
}

// ---------------- attention partial pass: tf32 mma flash-decoding ----------------
// dynamic smem (uint32 words):
//   qs[64][68]  (tf32)      off 0
//   ks[64][68]  (tf32)      off 4352
//   vs[64][72]  (tf32)      off 8704
//   ps[4][16][68] (tf32)    off 13312
#define AT_QS(r,c) dynu[(r) * 68 + (c)]
#define AT_KS(r,c) dynu[4352 + (r) * 68 + (c)]
#define AT_VS(r,c) dynu[8704 + (r) * 72 + (c)]
#define AT_PS(w,r,c) dynu[13312 + (w) * (16*68) + (r) * 68 + (c)]
#define AT_SMEM_BYTES ((13312 + 4 * 16 * 68) * 4)

__global__ void __launch_bounds__(128)
attn_mma(const float* __restrict__ q, const float* __restrict__ kvp) {
    extern __shared__ uint32_t dynu[];
    const int sp = blockIdx.x, h = blockIdx.y, bt = blockIdx.z;
    const int tid = threadIdx.x, lane = tid & 31, warp = tid >> 5;
    const int g = lane >> 2, t = lane & 3;
    const int m0 = warp * 16;

    // load q tile (64 x 64) as tf32
    #pragma unroll
    for (int i = 0; i < 8; i++) {
        int slot = tid + i * 128;
        int r = slot >> 4, c4 = (slot & 15) * 4;
        float4 v = *(const float4*)(q + ((size_t)bt * NLTN + r) * DEMB + h * DHEAD + c4);
        uint4 u; u.x = f2tf32(v.x); u.y = f2tf32(v.y); u.z = f2tf32(v.z); u.w = f2tf32(v.w);
        *(uint4*)&AT_QS(r, c4) = u;
    }

    float m1 = -CUDART_INF_F, m2 = -CUDART_INF_F, l1 = 0.f, l2 = 0.f;
    float o[8][4];
    #pragma unroll
    for (int nt = 0; nt < 8; nt++)
        #pragma unroll
        for (int e = 0; e < 4; e++) o[nt][e] = 0.f;

    const float* kvbase = kvp + (size_t)bt * NCTX * (2 * DEMB);
    __syncthreads();

    for (int ti = sp; ti < KTILES; ti += NSPLIT) {
        const int j0 = ti * 64;
        // load k, v tiles (64 keys x 64 d) as tf32
        #pragma unroll
        for (int i = 0; i < 8; i++) {
            int slot = tid + i * 128;
            int key = slot >> 4, c4 = (slot & 15) * 4;
            const float* row = kvbase + (size_t)(j0 + key) * (2 * DEMB) + h * DHEAD + c4;
            float4 kvv = *(const float4*)row;
            float4 vvv = *(const float4*)(row + DEMB);
            uint4 uk; uk.x = f2tf32(kvv.x); uk.y = f2tf32(kvv.y); uk.z = f2tf32(kvv.z); uk.w = f2tf32(kvv.w);
            uint4 uv; uv.x = f2tf32(vvv.x); uv.y = f2tf32(vvv.y); uv.z = f2tf32(vvv.z); uv.w = f2tf32(vvv.w);
            *(uint4*)&AT_KS(key, c4) = uk;
            *(uint4*)&AT_VS(key, c4) = uv;
        }
        __syncthreads();

        // scores: s[16x64] = q_warp @ k^T
        float sc[8][4];
        #pragma unroll
        for (int nt = 0; nt < 8; nt++)
            #pragma unroll
            for (int e = 0; e < 4; e++) sc[nt][e] = 0.f;
        #pragma unroll
        for (int ks8 = 0; ks8 < 8; ks8++) {
            const int k8 = ks8 * 8;
            uint32_t af[4];
            af[0] = AT_QS(m0 + g,     k8 + t);
            af[1] = AT_QS(m0 + g + 8, k8 + t);
            af[2] = AT_QS(m0 + g,     k8 + t + 4);
            af[3] = AT_QS(m0 + g + 8, k8 + t + 4);
            #pragma unroll
            for (int nt = 0; nt < 8; nt++) {
                uint32_t bf[2];
                bf[0] = AT_KS(nt * 8 + g, k8 + t);
                bf[1] = AT_KS(nt * 8 + g, k8 + t + 4);
                mma_tf32(sc[nt], af, bf);
            }
        }
        // softmax update (rows g and g+8)
        float mx1 = -CUDART_INF_F, mx2 = -CUDART_INF_F;
        #pragma unroll
        for (int nt = 0; nt < 8; nt++) {
            sc[nt][0] *= 0.125f; sc[nt][1] *= 0.125f;
            sc[nt][2] *= 0.125f; sc[nt][3] *= 0.125f;
            mx1 = fmaxf(mx1, fmaxf(sc[nt][0], sc[nt][1]));
            mx2 = fmaxf(mx2, fmaxf(sc[nt][2], sc[nt][3]));
        }
        #pragma unroll
        for (int off = 1; off <= 2; off <<= 1) {
            mx1 = fmaxf(mx1, __shfl_xor_sync(~0u, mx1, off));
            mx2 = fmaxf(mx2, __shfl_xor_sync(~0u, mx2, off));
        }
        float mn1 = fmaxf(m1, mx1), mn2 = fmaxf(m2, mx2);
        float fac1 = __expf(m1 - mn1), fac2 = __expf(m2 - mn2);
        float s1 = 0.f, s2 = 0.f;
        #pragma unroll
        for (int nt = 0; nt < 8; nt++) {
            sc[nt][0] = __expf(sc[nt][0] - mn1);
            sc[nt][1] = __expf(sc[nt][1] - mn1);
            sc[nt][2] = __expf(sc[nt][2] - mn2);
            sc[nt][3] = __expf(sc[nt][3] - mn2);
            s1 += sc[nt][0] + sc[nt][1];
            s2 += sc[nt][2] + sc[nt][3];
        }
        #pragma unroll
        for (int off = 1; off <= 2; off <<= 1) {
            s1 += __shfl_xor_sync(~0u, s1, off);
            s2 += __shfl_xor_sync(~0u, s2, off);
        }
        l1 = l1 * fac1 + s1; m1 = mn1;
        l2 = l2 * fac2 + s2; m2 = mn2;
        #pragma unroll
        for (int nt = 0; nt < 8; nt++) {
            o[nt][0] *= fac1; o[nt][1] *= fac1;
            o[nt][2] *= fac2; o[nt][3] *= fac2;
        }
        // store p (tf32) to per-warp slab
        #pragma unroll
        for (int nt = 0; nt < 8; nt++) {
            AT_PS(warp, g,     nt * 8 + 2 * t)     = f2tf32(sc[nt][0]);
            AT_PS(warp, g,     nt * 8 + 2 * t + 1) = f2tf32(sc[nt][1]);
            AT_PS(warp, g + 8, nt * 8 + 2 * t)     = f2tf32(sc[nt][2]);
            AT_PS(warp, g + 8, nt * 8 + 2 * t + 1) = f2tf32(sc[nt][3]);
        }
        __syncwarp();
        // o += p @ v
        #pragma unroll
        for (int ks8 = 0; ks8 < 8; ks8++) {
            const int k8 = ks8 * 8;
            uint32_t af[4];
            af[0] = AT_PS(warp, g,     k8 + t);
            af[1] = AT_PS(warp, g + 8, k8 + t);
            af[2] = AT_PS(warp, g,     k8 + t + 4);
            af[3] = AT_PS(warp, g + 8, k8 + t + 4);
            #pragma unroll
            for (int nt = 0; nt < 8; nt++) {
                uint32_t bf[2];
                bf[0] = AT_VS(k8 + t,     nt * 8 + g);
                bf[1] = AT_VS(k8 + t + 4, nt * 8 + g);
                mma_tf32(o[nt], af, bf);
            }
        }
        __syncthreads();   // before next tile overwrites ks/vs
    }

    // write partials
    const int base = (bt * HEADS + h) * NSPLIT + sp;
    const int r1 = m0 + g, r2 = m0 + g + 8;
    if (t == 0) {
        g_pm[base * NLTN + r1] = m1;  g_pl[base * NLTN + r1] = l1;
        g_pm[base * NLTN + r2] = m2;  g_pl[base * NLTN + r2] = l2;
    }
    float* p1 = g_po + ((size_t)base * NLTN + r1) * DHEAD + 2 * t;
    float* p2 = g_po + ((size_t)base * NLTN + r2) * DHEAD + 2 * t;
    #pragma unroll
    for (int nt = 0; nt < 8; nt++) {
        *(float2*)(p1 + nt * 8) = make_float2(o[nt][0], o[nt][1]);
        *(float2*)(p2 + nt * 8) = make_float2(o[nt][2], o[nt][3]);
    }
}

// ---------------- combine partials ----------------
__global__ void __launch_bounds__(256) attn_combine() {
    int bh = blockIdx.x;
    int bt = bh / HEADS, h = bh % HEADS;
    __shared__ float ws[NLTN][NSPLIT];
    __shared__ float linv[NLTN];
    int tid = threadIdx.x;
    if (tid < NLTN) {
        int row = tid;
        float m = -CUDART_INF_F;
        #pragma unroll
        for (int s = 0; s < NSPLIT; s++)
            m = fmaxf(m, g_pm[(bh * NSPLIT + s) * NLTN + row]);
        float L = 0.f;
        #pragma unroll
        for (int s = 0; s < NSPLIT; s++) {
            float w = __expf(g_pm[(bh * NSPLIT + s) * NLTN + row] - m);
            ws[row][s] = w;
            L += g_pl[(bh * NSPLIT + s) * NLTN + row] * w;
        }
        linv[row] = 1.f / L;
    }
    __syncthreads();
    for (int i = tid; i < NLTN * DHEAD; i += 256) {
        int row = i >> 6, d = i & 63;
        float acc = 0.f;
        #pragma unroll
        for (int s = 0; s < NSPLIT; s++)
            acc += g_po[(((size_t)bh * NSPLIT + s) * NLTN + row) * DHEAD + d] * ws[row][s];
        g_attnout[((size_t)bt * NLTN + row) * DEMB + h * DHEAD + d] = acc * linv[row];
    }
}

extern "C" void kernel_launch(void* const* d_in, const int* in_sizes, int n_in,
                              void* d_out, int out_size) {
    const float* src   = (const float*)d_in[0];
    const float* ltn   = (const float*)d_in[1];
    const float* gsrc  = (const float*)d_in[2];
    const float* bsrc  = (const float*)d_in[3];
    const float* gltn  = (const float*)d_in[4];
    const float* bltn  = (const float*)d_in[5];
    const float* Wq    = (const float*)d_in[6];
    const float* Wkv   = (const float*)d_in[7];
    const float* Wo    = (const float*)d_in[8];
    float* out = (float*)d_out;

    float *p_ltn_n, *p_q, *p_kv, *p_stats, *p_attn;
    cudaGetSymbolAddress((void**)&p_ltn_n, g_ltn_n);
    cudaGetSymbolAddress((void**)&p_q,     g_q);
    cudaGetSymbolAddress((void**)&p_kv,    g_kv);
    cudaGetSymbolAddress((void**)&p_stats, g_stats);
    cudaGetSymbolAddress((void**)&p_attn,  g_attnout);

    cudaFuncSetAttribute(kv_src_tf32, cudaFuncAttributeMaxDynamicSharedMemorySize, KV_SMEM_BYTES);
    cudaFuncSetAttribute(attn_mma,    cudaFuncAttributeMaxDynamicSharedMemorySize, AT_SMEM_BYTES);

    // 1) LN(ltn) and src row stats
    ln_ltn_kernel<<<BT * NLTN, 256>>>(ltn, gltn, bltn);
    src_stats_kernel<<<BT * NSRC / 8, 256>>>(src);

    // 2) q = ltn_n @ Wq (fp32, exact)
    sgemm128<<<dim3(DEMB / 128, (BT * NLTN) / 128), 256>>>(
        p_ltn_n, Wq, p_q, DIM, DEMB, BT * NLTN, 0, 0);

    // 3) kv (src rows, fused LN): tf32 tensor cores, async pipelined
    kv_src_tf32<<<dim3(1024 / 128, (BT * NSRC) / 128), 256, KV_SMEM_BYTES>>>(
        src, Wkv, p_kv, p_stats, gsrc, bsrc);

    // 4) kv (ltn rows): appended at row 8192 of each bt chunk (fp32)
    sgemm128<<<dim3(1024 / 128, (BT * NLTN) / 128), 256>>>(
        p_ltn_n, Wkv, p_kv, DIM, 2 * DEMB, NLTN, NSRC, NCTX);

    // 5) attention: tf32 mma split-KV + combine
    attn_mma<<<dim3(NSPLIT, HEADS, BT), 128, AT_SMEM_BYTES>>>(p_q, p_kv);
    attn_combine<<<BT * HEADS, 256>>>();

    // 6) out = attn_out @ Wo (fp32)
    sgemm128<<<dim3(DIM / 128, (BT * NLTN) / 128), 256>>>(
        p_attn, Wo, out, DEMB, DIM, BT * NLTN, 0, 0);
}

// round 5
// speedup vs baseline: 2.9421x; 1.1109x over previous
#include <cuda_runtime.h>
#include <math_constants.h>
#include <cstdint>

#define BT     8        // b*t
#define NSRC   8192
#define NLTN   64
#define NCTX   8256     // NSRC + NLTN
#define DIM    768
#define DEMB   512
#define HEADS  8
#define DHEAD  64
#define NSPLIT 32
#define KTILES 129      // NCTX / 64
#define EPS    1e-5f

// ---- scratch (device globals: no allocation allowed) ----
__device__ float    g_ltn_n[BT * NLTN * DIM];
__device__ float    g_q[BT * NLTN * DEMB];
__device__ float    g_kv[BT * NCTX * 2 * DEMB];       // 270 MB, tf32 bits
__device__ uint32_t g_srcn[BT * NSRC * DIM];          // 201 MB, normalized src (tf32)
__device__ uint32_t g_wkvt[DIM * 2 * DEMB];           // Wkv as tf32
__device__ float    g_attnout[BT * NLTN * DEMB];
__device__ float    g_po[BT * HEADS * NSPLIT * NLTN * DHEAD];
__device__ float    g_pm[BT * HEADS * NSPLIT * NLTN];
__device__ float    g_pl[BT * HEADS * NSPLIT * NLTN];

// ---------------- helpers ----------------
__device__ __forceinline__ uint32_t f2tf32(float f) {
    uint32_t u;
    asm("cvt.rna.tf32.f32 %0, %1;" : "=r"(u) : "f"(f));
    return u;
}
__device__ __forceinline__ void mma_tf32(float* d, const uint32_t* a, const uint32_t* b) {
    asm volatile(
        "mma.sync.aligned.m16n8k8.row.col.f32.tf32.tf32.f32 "
        "{%0,%1,%2,%3}, {%4,%5,%6,%7}, {%8,%9}, {%0,%1,%2,%3};\n"
        : "+f"(d[0]), "+f"(d[1]), "+f"(d[2]), "+f"(d[3])
        : "r"(a[0]), "r"(a[1]), "r"(a[2]), "r"(a[3]), "r"(b[0]), "r"(b[1]));
}
__device__ __forceinline__ void cp16(void* dst_smem, const void* src) {
    uint32_t d = (uint32_t)__cvta_generic_to_shared(dst_smem);
    asm volatile("cp.async.cg.shared.global [%0], [%1], 16;" :: "r"(d), "l"(src));
}
#define CP_COMMIT() asm volatile("cp.async.commit_group;")
#define CP_WAIT1()  asm volatile("cp.async.wait_group 1;")
#define CP_WAIT0()  asm volatile("cp.async.wait_group 0;")

// ---------------- LayerNorm of ltn (512 rows) ----------------
__global__ void ln_ltn_kernel(const float* __restrict__ ltn,
                              const float* __restrict__ g,
                              const float* __restrict__ b) {
    int row = blockIdx.x;
    const float* x = ltn + (size_t)row * DIM;
    int tid = threadIdx.x;
    float v0 = x[tid], v1 = x[tid + 256], v2 = x[tid + 512];
    float s  = v0 + v1 + v2;
    float s2 = v0 * v0 + v1 * v1 + v2 * v2;
    __shared__ float red[2][8];
    #pragma unroll
    for (int o = 16; o; o >>= 1) {
        s  += __shfl_xor_sync(~0u, s,  o);
        s2 += __shfl_xor_sync(~0u, s2, o);
    }
    int w = tid >> 5, l = tid & 31;
    if (l == 0) { red[0][w] = s; red[1][w] = s2; }
    __syncthreads();
    s = 0.f; s2 = 0.f;
    #pragma unroll
    for (int i = 0; i < 8; i++) { s += red[0][i]; s2 += red[1][i]; }
    float mean = s * (1.f / DIM);
    float var  = s2 * (1.f / DIM) - mean * mean;
    float rstd = rsqrtf(var + EPS);
    float* out = g_ltn_n + (size_t)row * DIM;
    out[tid]       = (v0 - mean) * rstd * g[tid]       + b[tid];
    out[tid + 256] = (v1 - mean) * rstd * g[tid + 256] + b[tid + 256];
    out[tid + 512] = (v2 - mean) * rstd * g[tid + 512] + b[tid + 512];
}

// ---------------- normalize src -> tf32 (fused stats + LN + cvt) ----------------
__global__ void __launch_bounds__(256)
norm_src_tf32(const float* __restrict__ src,
              const float* __restrict__ g, const float* __restrict__ b) {
    int w = threadIdx.x >> 5, l = threadIdx.x & 31;
    int row = blockIdx.x * 8 + w;
    const float* x = src + (size_t)row * DIM;
    float4 v[6];
    float s = 0.f, s2 = 0.f;
    #pragma unroll
    for (int i = 0; i < 6; i++) {
        v[i] = *(const float4*)(x + i * 128 + l * 4);
        s  += v[i].x + v[i].y + v[i].z + v[i].w;
        s2 += v[i].x * v[i].x + v[i].y * v[i].y + v[i].z * v[i].z + v[i].w * v[i].w;
    }
    #pragma unroll
    for (int o = 16; o; o >>= 1) {
        s  += __shfl_xor_sync(~0u, s,  o);
        s2 += __shfl_xor_sync(~0u, s2, o);
    }
    float mean = s * (1.f / DIM);
    float var  = s2 * (1.f / DIM) - mean * mean;
    float rstd = rsqrtf(var + EPS);
    uint32_t* o = g_srcn + (size_t)row * DIM;
    #pragma unroll
    for (int i = 0; i < 6; i++) {
        int c = i * 128 + l * 4;
        float4 gg = *(const float4*)(g + c);
        float4 bb = *(const float4*)(b + c);
        uint4 u;
        u.x = f2tf32((v[i].x - mean) * rstd * gg.x + bb.x);
        u.y = f2tf32((v[i].y - mean) * rstd * gg.y + bb.y);
        u.z = f2tf32((v[i].z - mean) * rstd * gg.z + bb.z);
        u.w = f2tf32((v[i].w - mean) * rstd * gg.w + bb.w);
        *(uint4*)(o + c) = u;
    }
}

// ---------------- convert Wkv to tf32 ----------------
__global__ void cvt_wkv_tf32(const float* __restrict__ in) {
    int i = (blockIdx.x * 256 + threadIdx.x) * 4;
    float4 v = *(const float4*)(in + i);
    uint4 u;
    u.x = f2tf32(v.x); u.y = f2tf32(v.y); u.z = f2tf32(v.z); u.w = f2tf32(v.w);
    *(uint4*)(g_wkvt + i) = u;
}

// ---------------- KV projection (src rows): pure tf32 GEMM, cp.async 2-stage ----------------
// smem (uint32): As[2][128][36], Bs[2][32][136]   = 17920 words = 71.7 KB
#define KVS_A(b,r,c) dynu[(b) * (128*36) + (r) * 36 + (c)]
#define KVS_B(b,r,c) dynu[9216 + (b) * (32*136) + (r) * 136 + (c)]
#define KVS_SMEM_BYTES (17920 * 4)

__global__ void __launch_bounds__(256, 2)
kv_src_mm(const uint32_t* __restrict__ A, const uint32_t* __restrict__ W,
          float* __restrict__ C) {
    extern __shared__ uint32_t dynu[];
    const int tid = threadIdx.x;
    const int lane = tid & 31, warp = tid >> 5;
    const int row0 = blockIdx.y * 128, col0 = blockIdx.x * 128;
    const int N = 2 * DEMB;

    const int wm = warp & 3, wn = warp >> 2;
    const int m0w = wm * 32, n0w = wn * 64;
    const int g = lane >> 2, t = lane & 3;

    float acc[2][8][4];
    #pragma unroll
    for (int mt = 0; mt < 2; mt++)
        #pragma unroll
        for (int nt = 0; nt < 8; nt++)
            #pragma unroll
            for (int e = 0; e < 4; e++) acc[mt][nt][e] = 0.f;

    auto prefetch = [&](int buf, int c) {
        int k0 = c * 32;
        #pragma unroll
        for (int i = 0; i < 4; i++) {
            int slot = tid + i * 256;
            int r = slot >> 3, c4 = (slot & 7) * 4;
            cp16(&KVS_A(buf, r, c4), A + (size_t)(row0 + r) * DIM + k0 + c4);
        }
        #pragma unroll
        for (int i = 0; i < 4; i++) {
            int slot = tid + i * 256;
            int r = slot >> 5, c4 = (slot & 31) * 4;
            cp16(&KVS_B(buf, r, c4), W + (size_t)(k0 + r) * N + col0 + c4);
        }
    };

    prefetch(0, 0);
    CP_COMMIT();

    for (int c = 0; c < 24; c++) {
        if (c < 23) { prefetch((c + 1) & 1, c + 1); CP_COMMIT(); CP_WAIT1(); }
        else        { CP_WAIT0(); }
        __syncthreads();

        const int b = c & 1;
        #pragma unroll
        for (int ks8 = 0; ks8 < 4; ks8++) {
            const int k8 = ks8 * 8;
            uint32_t af[2][4];
            #pragma unroll
            for (int mt = 0; mt < 2; mt++) {
                int r = m0w + mt * 16 + g;
                af[mt][0] = KVS_A(b, r,     k8 + t);
                af[mt][1] = KVS_A(b, r + 8, k8 + t);
                af[mt][2] = KVS_A(b, r,     k8 + t + 4);
                af[mt][3] = KVS_A(b, r + 8, k8 + t + 4);
            }
            #pragma unroll
            for (int nt = 0; nt < 8; nt++) {
                uint32_t bf[2];
                int cc = n0w + nt * 8 + g;
                bf[0] = KVS_B(b, k8 + t,     cc);
                bf[1] = KVS_B(b, k8 + 4 + t, cc);
                mma_tf32(acc[0][nt], af[0], bf);
                mma_tf32(acc[1][nt], af[1], bf);
            }
        }
        __syncthreads();
    }

    // epilogue: write tf32-rounded bits (attention consumes them directly)
    const int bt  = row0 / NSRC;
    const int rin = row0 % NSRC;
    const size_t crow0 = (size_t)bt * NCTX + rin;
    #pragma unroll
    for (int mt = 0; mt < 2; mt++) {
        int r = m0w + mt * 16 + g;
        float* c0 = C + (crow0 + r) * (size_t)N + col0 + n0w + 2 * t;
        float* c1 = c0 + 8 * (size_t)N;
        #pragma unroll
        for (int nt = 0; nt < 8; nt++) {
            *(float2*)(c0 + nt * 8) = make_float2(__uint_as_float(f2tf32(acc[mt][nt][0])),
                                                  __uint_as_float(f2tf32(acc[mt][nt][1])));
            *(float2*)(c1 + nt * 8) = make_float2(__uint_as_float(f2tf32(acc[mt][nt][2])),
                                                  __uint_as_float(f2tf32(acc[mt][nt][3])));
        }
    }
}

// ---------------- classic 128x128x8 SGEMM (fp32); CVT rounds output to tf32 ----------------
template <bool CVT>
__global__ void __launch_bounds__(256)
sgemm128(const float* __restrict__ A, const float* __restrict__ W,
         float* __restrict__ C,
         int K, int N, int rows_per_bt, int out_off, int out_stride) {
    __shared__ float As[8][128];
    __shared__ float Bs[8][128];

    int tid = threadIdx.x;
    int row0 = blockIdx.y * 128, col0 = blockIdx.x * 128;

    int aRow = tid >> 1, aCol = (tid & 1) * 4;
    int bRow = tid >> 5, bCol = (tid & 31) * 4;
    const float* Aptr = A + (size_t)(row0 + aRow) * K;

    int tx = tid & 15, ty = tid >> 4;
    float acc[8][8];
    #pragma unroll
    for (int i = 0; i < 8; i++)
        #pragma unroll
        for (int j = 0; j < 8; j++) acc[i][j] = 0.f;

    for (int k0 = 0; k0 < K; k0 += 8) {
        float4 av = *(const float4*)(Aptr + k0 + aCol);
        As[aCol + 0][aRow] = av.x;
        As[aCol + 1][aRow] = av.y;
        As[aCol + 2][aRow] = av.z;
        As[aCol + 3][aRow] = av.w;
        float4 bv = *(const float4*)(W + (size_t)(k0 + bRow) * N + col0 + bCol);
        *(float4*)&Bs[bRow][bCol] = bv;
        __syncthreads();
        #pragma unroll
        for (int kk = 0; kk < 8; kk++) {
            float ar[8], br[8];
            *(float4*)(ar)     = *(const float4*)&As[kk][ty * 8];
            *(float4*)(ar + 4) = *(const float4*)&As[kk][ty * 8 + 4];
            *(float4*)(br)     = *(const float4*)&Bs[kk][tx * 8];
            *(float4*)(br + 4) = *(const float4*)&Bs[kk][tx * 8 + 4];
            #pragma unroll
            for (int i = 0; i < 8; i++)
                #pragma unroll
                for (int j = 0; j < 8; j++) acc[i][j] = fmaf(ar[i], br[j], acc[i][j]);
        }
        __syncthreads();
    }
    #pragma unroll
    for (int i = 0; i < 8; i++) {
        int grow = row0 + ty * 8 + i;
        int bt = grow / rows_per_bt;
        int r  = grow % rows_per_bt;
        int crow = bt * out_stride + out_off + r;
        float* cp = C + (size_t)crow * N + col0 + tx * 8;
        if (CVT) {
            float o[8];
            #pragma unroll
            for (int j = 0; j < 8; j++) o[j] = __uint_as_float(f2tf32(acc[i][j]));
            *(float4*)cp       = make_float4(o[0], o[1], o[2], o[3]);
            *(float4*)(cp + 4) = make_float4(o[4], o[5], o[6], o[7]);
        } else {
            *(float4*)cp       = make_float4(acc[i][0], acc[i][1], acc[i][2], acc[i][3]);
            *(float4*)(cp + 4) = make_float4(acc[i][4], acc[i][5], acc[i][6], acc[i][7]);
        }
    }
}

// ---------------- attention partial: tf32 mma, cp.async double-buffered kv ----------------
// smem words: qs[64][68] @0, ks[2][64][68] @4352, vs[2][64][72] @13056, ps[4][16][68] @22272
#define AT_QS(r,c)    dynu[(r) * 68 + (c)]
#define AT_KS(b,r,c)  dynu[4352  + (b) * 4352 + (r) * 68 + (c)]
#define AT_VS(b,r,c)  dynu[13056 + (b) * 4608 + (r) * 72 + (c)]
#define AT_PS(w,r,c)  dynu[22272 + (w) * 1088 + (r) * 68 + (c)]
#define AT_SMEM_BYTES (26624 * 4)

__global__ void __launch_bounds__(128)
attn_mma(const float* __restrict__ q, const uint32_t* __restrict__ kvp) {
    extern __shared__ uint32_t dynu[];
    const int sp = blockIdx.x, h = blockIdx.y, bt = blockIdx.z;
    const int tid = threadIdx.x, lane = tid & 31, warp = tid >> 5;
    const int g = lane >> 2, t = lane & 3;
    const int m0 = warp * 16;
    const uint32_t* kvbase = kvp + (size_t)bt * NCTX * (2 * DEMB) + h * DHEAD;

    auto prefetch_kv = [&](int buf, int ti) {
        int j0 = ti * 64;
        #pragma unroll
        for (int i = 0; i < 8; i++) {
            int slot = tid + i * 128;
            int key = slot >> 4, c4 = (slot & 15) * 4;
            const uint32_t* row = kvbase + (size_t)(j0 + key) * (2 * DEMB) + c4;
            cp16(&AT_KS(buf, key, c4), row);
            cp16(&AT_VS(buf, key, c4), row + DEMB);
        }
    };

    prefetch_kv(0, sp);
    CP_COMMIT();

    // stage q tile (64 x 64) as tf32
    #pragma unroll
    for (int i = 0; i < 8; i++) {
        int slot = tid + i * 128;
        int r = slot >> 4, c4 = (slot & 15) * 4;
        float4 v = *(const float4*)(q + ((size_t)bt * NLTN + r) * DEMB + h * DHEAD + c4);
        uint4 u; u.x = f2tf32(v.x); u.y = f2tf32(v.y); u.z = f2tf32(v.z); u.w = f2tf32(v.w);
        *(uint4*)&AT_QS(r, c4) = u;
    }

    float m1 = -CUDART_INF_F, m2 = -CUDART_INF_F, l1 = 0.f, l2 = 0.f;
    float o[8][4];
    #pragma unroll
    for (int nt = 0; nt < 8; nt++)
        #pragma unroll
        for (int e = 0; e < 4; e++) o[nt][e] = 0.f;

    int cnt = 0;
    for (int ti = sp; ti < KTILES; ti += NSPLIT, cnt++) {
        int nxt = ti + NSPLIT;
        if (nxt < KTILES) { prefetch_kv((cnt + 1) & 1, nxt); CP_COMMIT(); CP_WAIT1(); }
        else              { CP_WAIT0(); }
        __syncthreads();
        const int b = cnt & 1;

        // scores: s[16x64] = q_warp @ k^T
        float sc[8][4];
        #pragma unroll
        for (int nt = 0; nt < 8; nt++)
            #pragma unroll
            for (int e = 0; e < 4; e++) sc[nt][e] = 0.f;
        #pragma unroll
        for (int ks8 = 0; ks8 < 8; ks8++) {
            const int k8 = ks8 * 8;
            uint32_t af[4];
            af[0] = AT_QS(m0 + g,     k8 + t);
            af[1] = AT_QS(m0 + g + 8, k8 + t);
            af[2] = AT_QS(m0 + g,     k8 + t + 4);
            af[3] = AT_QS(m0 + g + 8, k8 + t + 4);
            #pragma unroll
            for (int nt = 0; nt < 8; nt++) {
                uint32_t bf[2];
                bf[0] = AT_KS(b, nt * 8 + g, k8 + t);
                bf[1] = AT_KS(b, nt * 8 + g, k8 + t + 4);
                mma_tf32(sc[nt], af, bf);
            }
        }
        // online softmax (rows g and g+8)
        float mx1 = -CUDART_INF_F, mx2 = -CUDART_INF_F;
        #pragma unroll
        for (int nt = 0; nt < 8; nt++) {
            sc[nt][0] *= 0.125f; sc[nt][1] *= 0.125f;
            sc[nt][2] *= 0.125f; sc[nt][3] *= 0.125f;
            mx1 = fmaxf(mx1, fmaxf(sc[nt][0], sc[nt][1]));
            mx2 = fmaxf(mx2, fmaxf(sc[nt][2], sc[nt][3]));
        }
        #pragma unroll
        for (int off = 1; off <= 2; off <<= 1) {
            mx1 = fmaxf(mx1, __shfl_xor_sync(~0u, mx1, off));
            mx2 = fmaxf(mx2, __shfl_xor_sync(~0u, mx2, off));
        }
        float mn1 = fmaxf(m1, mx1), mn2 = fmaxf(m2, mx2);
        float fac1 = __expf(m1 - mn1), fac2 = __expf(m2 - mn2);
        float s1 = 0.f, s2 = 0.f;
        #pragma unroll
        for (int nt = 0; nt < 8; nt++) {
            sc[nt][0] = __expf(sc[nt][0] - mn1);
            sc[nt][1] = __expf(sc[nt][1] - mn1);
            sc[nt][2] = __expf(sc[nt][2] - mn2);
            sc[nt][3] = __expf(sc[nt][3] - mn2);
            s1 += sc[nt][0] + sc[nt][1];
            s2 += sc[nt][2] + sc[nt][3];
        }
        #pragma unroll
        for (int off = 1; off <= 2; off <<= 1) {
            s1 += __shfl_xor_sync(~0u, s1, off);
            s2 += __shfl_xor_sync(~0u, s2, off);
        }
        l1 = l1 * fac1 + s1; m1 = mn1;
        l2 = l2 * fac2 + s2; m2 = mn2;
        #pragma unroll
        for (int nt = 0; nt < 8; nt++) {
            o[nt][0] *= fac1; o[nt][1] *= fac1;
            o[nt][2] *= fac2; o[nt][3] *= fac2;
        }
        // p -> per-warp slab (tf32)
        #pragma unroll
        for (int nt = 0; nt < 8; nt++) {
            AT_PS(warp, g,     nt * 8 + 2 * t)     = f2tf32(sc[nt][0]);
            AT_PS(warp, g,     nt * 8 + 2 * t + 1) = f2tf32(sc[nt][1]);
            AT_PS(warp, g + 8, nt * 8 + 2 * t)     = f2tf32(sc[nt][2]);
            AT_PS(warp, g + 8, nt * 8 + 2 * t + 1) = f2tf32(sc[nt][3]);
        }
        __syncwarp();
        // o += p @ v
        #pragma unroll
        for (int ks8 = 0; ks8 < 8; ks8++) {
            const int k8 = ks8 * 8;
            uint32_t af[4];
            af[0] = AT_PS(warp, g,     k8 + t);
            af[1] = AT_PS(warp, g + 8, k8 + t);
            af[2] = AT_PS(warp, g,     k8 + t + 4);
            af[3] = AT_PS(warp, g + 8, k8 + t + 4);
            #pragma unroll
            for (int nt = 0; nt < 8; nt++) {
                uint32_t bf[2];
                bf[0] = AT_VS(b, k8 + t,     nt * 8 + g);
                bf[1] = AT_VS(b, k8 + t + 4, nt * 8 + g);
                mma_tf32(o[nt], af, bf);
            }
        }
        __syncthreads();
    }

    // write partials
    const int base = (bt * HEADS + h) * NSPLIT + sp;
    const int r1 = m0 + g, r2 = m0 + g + 8;
    if (t == 0) {
        g_pm[base * NLTN + r1] = m1;  g_pl[base * NLTN + r1] = l1;
        g_pm[base * NLTN + r2] = m2;  g_pl[base * NLTN + r2] = l2;
    }
    float* p1 = g_po + ((size_t)base * NLTN + r1) * DHEAD + 2 * t;
    float* p2 = g_po + ((size_t)base * NLTN + r2) * DHEAD + 2 * t;
    #pragma unroll
    for (int nt = 0; nt < 8; nt++) {
        *(float2*)(p1 + nt * 8) = make_float2(o[nt][0], o[nt][1]);
        *(float2*)(p2 + nt * 8) = make_float2(o[nt][2], o[nt][3]);
    }
}

// ---------------- combine partials ----------------
__global__ void __launch_bounds__(256) attn_combine() {
    int bh = blockIdx.x;
    int bt = bh / HEADS, h = bh % HEADS;
    __shared__ float ws[NLTN][NSPLIT];
    __shared__ float linv[NLTN];
    int tid = threadIdx.x;
    if (tid < NLTN) {
        int row = tid;
        float m = -CUDART_INF_F;
        #pragma unroll
        for (int s = 0; s < NSPLIT; s++)
            m = fmaxf(m, g_pm[(bh * NSPLIT + s) * NLTN + row]);
        float L = 0.f;
        #pragma unroll
        for (int s = 0; s < NSPLIT; s++) {
            float w = __expf(g_pm[(bh * NSPLIT + s) * NLTN + row] - m);
            ws[row][s] = w;
            L += g_pl[(bh * NSPLIT + s) * NLTN + row] * w;
        }
        linv[row] = 1.f / L;
    }
    __syncthreads();
    for (int i = tid; i < NLTN * DHEAD; i += 256) {
        int row = i >> 6, d = i & 63;
        float acc = 0.f;
        #pragma unroll
        for (int s = 0; s < NSPLIT; s++)
            acc += g_po[(((size_t)bh * NSPLIT + s) * NLTN + row) * DHEAD + d] * ws[row][s];
        g_attnout[((size_t)bt * NLTN + row) * DEMB + h * DHEAD + d] = acc * linv[row];
    }
}

extern "C" void kernel_launch(void* const* d_in, const int* in_sizes, int n_in,
                              void* d_out, int out_size) {
    const float* src   = (const float*)d_in[0];
    const float* ltn   = (const float*)d_in[1];
    const float* gsrc  = (const float*)d_in[2];
    const float* bsrc  = (const float*)d_in[3];
    const float* gltn  = (const float*)d_in[4];
    const float* bltn  = (const float*)d_in[5];
    const float* Wq    = (const float*)d_in[6];
    const float* Wkv   = (const float*)d_in[7];
    const float* Wo    = (const float*)d_in[8];
    float* out = (float*)d_out;

    float *p_ltn_n, *p_q, *p_kv, *p_attn;
    uint32_t *p_srcn, *p_wkvt;
    cudaGetSymbolAddress((void**)&p_ltn_n, g_ltn_n);
    cudaGetSymbolAddress((void**)&p_q,     g_q);
    cudaGetSymbolAddress((void**)&p_kv,    g_kv);
    cudaGetSymbolAddress((void**)&p_attn,  g_attnout);
    cudaGetSymbolAddress((void**)&p_srcn,  g_srcn);
    cudaGetSymbolAddress((void**)&p_wkvt,  g_wkvt);

    cudaFuncSetAttribute(kv_src_mm, cudaFuncAttributeMaxDynamicSharedMemorySize, KVS_SMEM_BYTES);
    cudaFuncSetAttribute(attn_mma,  cudaFuncAttributeMaxDynamicSharedMemorySize, AT_SMEM_BYTES);

    // 1) preprocessing: LN(ltn), normalized-tf32 src, tf32 Wkv
    ln_ltn_kernel<<<BT * NLTN, 256>>>(ltn, gltn, bltn);
    norm_src_tf32<<<BT * NSRC / 8, 256>>>(src, gsrc, bsrc);
    cvt_wkv_tf32<<<(DIM * 2 * DEMB) / 1024, 256>>>(Wkv);

    // 2) q = ltn_n @ Wq (fp32, exact)
    sgemm128<false><<<dim3(DEMB / 128, (BT * NLTN) / 128), 256>>>(
        p_ltn_n, Wq, p_q, DIM, DEMB, BT * NLTN, 0, 0);

    // 3) kv (src rows): pure tf32 GEMM, async pipelined
    kv_src_mm<<<dim3(1024 / 128, (BT * NSRC) / 128), 256, KVS_SMEM_BYTES>>>(
        p_srcn, p_wkvt, p_kv);

    // 4) kv (ltn rows): fp32 GEMM, tf32-rounded output
    sgemm128<true><<<dim3(1024 / 128, (BT * NLTN) / 128), 256>>>(
        p_ltn_n, Wkv, p_kv, DIM, 2 * DEMB, NLTN, NSRC, NCTX);

    // 5) attention: tf32 mma split-KV + combine
    attn_mma<<<dim3(NSPLIT, HEADS, BT), 128, AT_SMEM_BYTES>>>(p_q, (const uint32_t*)p_kv);
    attn_combine<<<BT * HEADS, 256>>>();

    // 6) out = attn_out @ Wo (fp32)
    sgemm128<false><<<dim3(DIM / 128, (BT * NLTN) / 128), 256>>>(
        p_attn, Wo, out, DEMB, DIM, BT * NLTN, 0, 0);
}

// round 7
// speedup vs baseline: 4.0450x; 1.3749x over previous
#include <cuda_runtime.h>
#include <math_constants.h>
#include <cstdint>

#define BT     8        // b*t
#define NSRC   8192
#define NLTN   64
#define NCTX   8256     // NSRC + NLTN
#define DIM    768
#define DEMB   512
#define HEADS  8
#define DHEAD  64
#define NSPLIT 32
#define KTILES 129      // NCTX / 64
#define EPS    1e-5f

// ---- scratch (device globals: no allocation allowed) ----
__device__ uint32_t g_ltn_t[BT * NLTN * DIM];         // LN(ltn) as tf32
__device__ float    g_q[BT * NLTN * DEMB];
__device__ float    g_kv[BT * NCTX * 2 * DEMB];       // 270 MB, tf32 bits
__device__ uint32_t g_srcn[BT * NSRC * DIM];          // 201 MB, normalized src (tf32)
__device__ uint32_t g_wkvt[DIM * 2 * DEMB];           // Wkv as tf32
__device__ uint32_t g_wqt[DIM * DEMB];                // Wq  as tf32
__device__ uint32_t g_wot[DEMB * DIM];                // Wo  as tf32
__device__ uint32_t g_attn_t[BT * NLTN * DEMB];       // attn out as tf32
__device__ float    g_po[BT * HEADS * NSPLIT * NLTN * DHEAD];
__device__ float    g_pm[BT * HEADS * NSPLIT * NLTN];
__device__ float    g_pl[BT * HEADS * NSPLIT * NLTN];

// ---------------- helpers ----------------
__device__ __forceinline__ uint32_t f2tf32(float f) {
    uint32_t u;
    asm("cvt.rna.tf32.f32 %0, %1;" : "=r"(u) : "f"(f));
    return u;
}
__device__ __forceinline__ void mma_tf32(float* d, const uint32_t* a, const uint32_t* b) {
    asm volatile(
        "mma.sync.aligned.m16n8k8.row.col.f32.tf32.tf32.f32 "
        "{%0,%1,%2,%3}, {%4,%5,%6,%7}, {%8,%9}, {%0,%1,%2,%3};\n"
        : "+f"(d[0]), "+f"(d[1]), "+f"(d[2]), "+f"(d[3])
        : "r"(a[0]), "r"(a[1]), "r"(a[2]), "r"(a[3]), "r"(b[0]), "r"(b[1]));
}
__device__ __forceinline__ void cp16(void* dst_smem, const void* src) {
    uint32_t d = (uint32_t)__cvta_generic_to_shared(dst_smem);
    asm volatile("cp.async.cg.shared.global [%0], [%1], 16;" :: "r"(d), "l"(src));
}
#define CP_COMMIT() asm volatile("cp.async.commit_group;")
#define CP_WAIT1()  asm volatile("cp.async.wait_group 1;")
#define CP_WAIT0()  asm volatile("cp.async.wait_group 0;")

// ---------------- LayerNorm of ltn -> tf32 (512 rows) ----------------
__global__ void ln_ltn_kernel(const float* __restrict__ ltn,
                              const float* __restrict__ g,
                              const float* __restrict__ b) {
    int row = blockIdx.x;
    const float* x = ltn + (size_t)row * DIM;
    int tid = threadIdx.x;
    float v0 = x[tid], v1 = x[tid + 256], v2 = x[tid + 512];
    float s  = v0 + v1 + v2;
    float s2 = v0 * v0 + v1 * v1 + v2 * v2;
    __shared__ float red[2][8];
    #pragma unroll
    for (int o = 16; o; o >>= 1) {
        s  += __shfl_xor_sync(~0u, s,  o);
        s2 += __shfl_xor_sync(~0u, s2, o);
    }
    int w = tid >> 5, l = tid & 31;
    if (l == 0) { red[0][w] = s; red[1][w] = s2; }
    __syncthreads();
    s = 0.f; s2 = 0.f;
    #pragma unroll
    for (int i = 0; i < 8; i++) { s += red[0][i]; s2 += red[1][i]; }
    float mean = s * (1.f / DIM);
    float var  = s2 * (1.f / DIM) - mean * mean;
    float rstd = rsqrtf(var + EPS);
    uint32_t* out = g_ltn_t + (size_t)row * DIM;
    out[tid]       = f2tf32((v0 - mean) * rstd * g[tid]       + b[tid]);
    out[tid + 256] = f2tf32((v1 - mean) * rstd * g[tid + 256] + b[tid + 256]);
    out[tid + 512] = f2tf32((v2 - mean) * rstd * g[tid + 512] + b[tid + 512]);
}

// ---------------- normalize src -> tf32 (fused stats + LN + cvt) ----------------
__global__ void __launch_bounds__(256)
norm_src_tf32(const float* __restrict__ src,
              const float* __restrict__ g, const float* __restrict__ b) {
    int w = threadIdx.x >> 5, l = threadIdx.x & 31;
    int row = blockIdx.x * 8 + w;
    const float* x = src + (size_t)row * DIM;
    float4 v[6];
    float s = 0.f, s2 = 0.f;
    #pragma unroll
    for (int i = 0; i < 6; i++) {
        v[i] = *(const float4*)(x + i * 128 + l * 4);
        s  += v[i].x + v[i].y + v[i].z + v[i].w;
        s2 += v[i].x * v[i].x + v[i].y * v[i].y + v[i].z * v[i].z + v[i].w * v[i].w;
    }
    #pragma unroll
    for (int o = 16; o; o >>= 1) {
        s  += __shfl_xor_sync(~0u, s,  o);
        s2 += __shfl_xor_sync(~0u, s2, o);
    }
    float mean = s * (1.f / DIM);
    float var  = s2 * (1.f / DIM) - mean * mean;
    float rstd = rsqrtf(var + EPS);
    uint32_t* o = g_srcn + (size_t)row * DIM;
    #pragma unroll
    for (int i = 0; i < 6; i++) {
        int c = i * 128 + l * 4;
        float4 gg = *(const float4*)(g + c);
        float4 bb = *(const float4*)(b + c);
        uint4 u;
        u.x = f2tf32((v[i].x - mean) * rstd * gg.x + bb.x);
        u.y = f2tf32((v[i].y - mean) * rstd * gg.y + bb.y);
        u.z = f2tf32((v[i].z - mean) * rstd * gg.z + bb.z);
        u.w = f2tf32((v[i].w - mean) * rstd * gg.w + bb.w);
        *(uint4*)(o + c) = u;
    }
}

// ---------------- convert fp32 weights to tf32 ----------------
__global__ void cvt_tf32(const float* __restrict__ in, uint32_t* __restrict__ out) {
    int i = (blockIdx.x * 256 + threadIdx.x) * 4;
    float4 v = *(const float4*)(in + i);
    uint4 u;
    u.x = f2tf32(v.x); u.y = f2tf32(v.y); u.z = f2tf32(v.z); u.w = f2tf32(v.w);
    *(uint4*)(out + i) = u;
}

// ---------------- KV projection (src rows): pure tf32 GEMM, cp.async 2-stage ----------------
#define KVS_A(b,r,c) dynu[(b) * (128*36) + (r) * 36 + (c)]
#define KVS_B(b,r,c) dynu[9216 + (b) * (32*136) + (r) * 136 + (c)]
#define KVS_SMEM_BYTES (17920 * 4)

__global__ void __launch_bounds__(256, 2)
kv_src_mm(const uint32_t* __restrict__ A, const uint32_t* __restrict__ W,
          float* __restrict__ C) {
    extern __shared__ uint32_t dynu[];
    const int tid = threadIdx.x;
    const int lane = tid & 31, warp = tid >> 5;
    const int row0 = blockIdx.y * 128, col0 = blockIdx.x * 128;
    const int N = 2 * DEMB;

    const int wm = warp & 3, wn = warp >> 2;
    const int m0w = wm * 32, n0w = wn * 64;
    const int g = lane >> 2, t = lane & 3;

    float acc[2][8][4];
    #pragma unroll
    for (int mt = 0; mt < 2; mt++)
        #pragma unroll
        for (int nt = 0; nt < 8; nt++)
            #pragma unroll
            for (int e = 0; e < 4; e++) acc[mt][nt][e] = 0.f;

    auto prefetch = [&](int buf, int c) {
        int k0 = c * 32;
        #pragma unroll
        for (int i = 0; i < 4; i++) {
            int slot = tid + i * 256;
            int r = slot >> 3, c4 = (slot & 7) * 4;
            cp16(&KVS_A(buf, r, c4), A + (size_t)(row0 + r) * DIM + k0 + c4);
        }
        #pragma unroll
        for (int i = 0; i < 4; i++) {
            int slot = tid + i * 256;
            int r = slot >> 5, c4 = (slot & 31) * 4;
            cp16(&KVS_B(buf, r, c4), W + (size_t)(k0 + r) * N + col0 + c4);
        }
    };

    prefetch(0, 0);
    CP_COMMIT();

    for (int c = 0; c < 24; c++) {
        if (c < 23) { prefetch((c + 1) & 1, c + 1); CP_COMMIT(); CP_WAIT1(); }
        else        { CP_WAIT0(); }
        __syncthreads();

        const int b = c & 1;
        #pragma unroll
        for (int ks8 = 0; ks8 < 4; ks8++) {
            const int k8 = ks8 * 8;
            uint32_t af[2][4];
            #pragma unroll
            for (int mt = 0; mt < 2; mt++) {
                int r = m0w + mt * 16 + g;
                af[mt][0] = KVS_A(b, r,     k8 + t);
                af[mt][1] = KVS_A(b, r + 8, k8 + t);
                af[mt][2] = KVS_A(b, r,     k8 + t + 4);
                af[mt][3] = KVS_A(b, r + 8, k8 + t + 4);
            }
            #pragma unroll
            for (int nt = 0; nt < 8; nt++) {
                uint32_t bf[2];
                int cc = n0w + nt * 8 + g;
                bf[0] = KVS_B(b, k8 + t,     cc);
                bf[1] = KVS_B(b, k8 + 4 + t, cc);
                mma_tf32(acc[0][nt], af[0], bf);
                mma_tf32(acc[1][nt], af[1], bf);
            }
        }
        __syncthreads();
    }

    const int bt  = row0 / NSRC;
    const int rin = row0 % NSRC;
    const size_t crow0 = (size_t)bt * NCTX + rin;
    #pragma unroll
    for (int mt = 0; mt < 2; mt++) {
        int r = m0w + mt * 16 + g;
        float* c0 = C + (crow0 + r) * (size_t)N + col0 + n0w + 2 * t;
        float* c1 = c0 + 8 * (size_t)N;
        #pragma unroll
        for (int nt = 0; nt < 8; nt++) {
            *(float2*)(c0 + nt * 8) = make_float2(__uint_as_float(f2tf32(acc[mt][nt][0])),
                                                  __uint_as_float(f2tf32(acc[mt][nt][1])));
            *(float2*)(c1 + nt * 8) = make_float2(__uint_as_float(f2tf32(acc[mt][nt][2])),
                                                  __uint_as_float(f2tf32(acc[mt][nt][3])));
        }
    }
}

// ---------------- small tf32 GEMM: 64x64 tiles, 4 warps, cp.async 2-stage ----------------
// OUT_TF32: round C to tf32 bits. Row remap: crow = (grow/rows_per_bt)*out_stride + out_off + grow%rows_per_bt
template <bool OUT_TF32>
__global__ void __launch_bounds__(128)
gemm64_tf32(const uint32_t* __restrict__ A, const uint32_t* __restrict__ W,
            float* __restrict__ C,
            int K, int N, int rows_per_bt, int out_off, int out_stride) {
    __shared__ uint32_t As[2][64][36];
    __shared__ uint32_t Bs[2][32][72];

    const int tid = threadIdx.x;
    const int lane = tid & 31, warp = tid >> 5;
    const int row0 = blockIdx.y * 64, col0 = blockIdx.x * 64;
    const int wm = warp & 1, wn = warp >> 1;
    const int m0w = wm * 32, n0w = wn * 32;
    const int g = lane >> 2, t = lane & 3;

    float acc[2][4][4];
    #pragma unroll
    for (int mt = 0; mt < 2; mt++)
        #pragma unroll
        for (int nt = 0; nt < 4; nt++)
            #pragma unroll
            for (int e = 0; e < 4; e++) acc[mt][nt][e] = 0.f;

    auto prefetch = [&](int buf, int c) {
        int k0 = c * 32;
        #pragma unroll
        for (int i = 0; i < 4; i++) {
            int slot = tid + i * 128;
            int r = slot >> 3, c4 = (slot & 7) * 4;
            cp16(&As[buf][r][c4], A + (size_t)(row0 + r) * K + k0 + c4);
        }
        #pragma unroll
        for (int i = 0; i < 4; i++) {
            int slot = tid + i * 128;
            int r = slot >> 4, c4 = (slot & 15) * 4;
            cp16(&Bs[buf][r][c4], W + (size_t)(k0 + r) * N + col0 + c4);
        }
    };

    const int NC = K / 32;
    prefetch(0, 0);
    CP_COMMIT();

    for (int c = 0; c < NC; c++) {
        if (c < NC - 1) { prefetch((c + 1) & 1, c + 1); CP_COMMIT(); CP_WAIT1(); }
        else            { CP_WAIT0(); }
        __syncthreads();

        const int b = c & 1;
        #pragma unroll
        for (int ks8 = 0; ks8 < 4; ks8++) {
            const int k8 = ks8 * 8;
            uint32_t af[2][4];
            #pragma unroll
            for (int mt = 0; mt < 2; mt++) {
                int r = m0w + mt * 16 + g;
                af[mt][0] = As[b][r][k8 + t];
                af[mt][1] = As[b][r + 8][k8 + t];
                af[mt][2] = As[b][r][k8 + t + 4];
                af[mt][3] = As[b][r + 8][k8 + t + 4];
            }
            #pragma unroll
            for (int nt = 0; nt < 4; nt++) {
                uint32_t bf[2];
                int cc = n0w + nt * 8 + g;
                bf[0] = Bs[b][k8 + t][cc];
                bf[1] = Bs[b][k8 + 4 + t][cc];
                mma_tf32(acc[0][nt], af[0], bf);
                mma_tf32(acc[1][nt], af[1], bf);
            }
        }
        __syncthreads();
    }

    #pragma unroll
    for (int mt = 0; mt < 2; mt++) {
        int grow = row0 + m0w + mt * 16 + g;
        int bt = grow / rows_per_bt;
        int r  = grow % rows_per_bt;
        size_t crow  = (size_t)bt * out_stride + out_off + r;
        int grow2 = grow + 8;
        int bt2 = grow2 / rows_per_bt;
        int r2  = grow2 % rows_per_bt;
        size_t crow2 = (size_t)bt2 * out_stride + out_off + r2;
        float* c0 = C + crow  * N + col0 + n0w + 2 * t;
        float* c1 = C + crow2 * N + col0 + n0w + 2 * t;
        #pragma unroll
        for (int nt = 0; nt < 4; nt++) {
            if (OUT_TF32) {
                *(float2*)(c0 + nt * 8) = make_float2(__uint_as_float(f2tf32(acc[mt][nt][0])),
                                                      __uint_as_float(f2tf32(acc[mt][nt][1])));
                *(float2*)(c1 + nt * 8) = make_float2(__uint_as_float(f2tf32(acc[mt][nt][2])),
                                                      __uint_as_float(f2tf32(acc[mt][nt][3])));
            } else {
                *(float2*)(c0 + nt * 8) = make_float2(acc[mt][nt][0], acc[mt][nt][1]);
                *(float2*)(c1 + nt * 8) = make_float2(acc[mt][nt][2], acc[mt][nt][3]);
            }
        }
    }
}

// ---------------- attention partial: tf32 mma, cp.async double-buffered kv ----------------
#define AT_QS(r,c)    dynu[(r) * 68 + (c)]
#define AT_KS(b,r,c)  dynu[4352  + (b) * 4352 + (r) * 68 + (c)]
#define AT_VS(b,r,c)  dynu[13056 + (b) * 4608 + (r) * 72 + (c)]
#define AT_PS(w,r,c)  dynu[22272 + (w) * 1088 + (r) * 68 + (c)]
#define AT_SMEM_BYTES (26624 * 4)

__global__ void __launch_bounds__(128)
attn_mma(const float* __restrict__ q, const uint32_t* __restrict__ kvp) {
    extern __shared__ uint32_t dynu[];
    const int sp = blockIdx.x, h = blockIdx.y, bt = blockIdx.z;
    const int tid = threadIdx.x, lane = tid & 31, warp = tid >> 5;
    const int g = lane >> 2, t = lane & 3;
    const int m0 = warp * 16;
    const uint32_t* kvbase = kvp + (size_t)bt * NCTX * (2 * DEMB) + h * DHEAD;

    auto prefetch_kv = [&](int buf, int ti) {
        int j0 = ti * 64;
        #pragma unroll
        for (int i = 0; i < 8; i++) {
            int slot = tid + i * 128;
            int key = slot >> 4, c4 = (slot & 15) * 4;
            const uint32_t* row = kvbase + (size_t)(j0 + key) * (2 * DEMB) + c4;
            cp16(&AT_KS(buf, key, c4), row);
            cp16(&AT_VS(buf, key, c4), row + DEMB);
        }
    };

    prefetch_kv(0, sp);
    CP_COMMIT();

    #pragma unroll
    for (int i = 0; i < 8; i++) {
        int slot = tid + i * 128;
        int r = slot >> 4, c4 = (slot & 15) * 4;
        float4 v = *(const float4*)(q + ((size_t)bt * NLTN + r) * DEMB + h * DHEAD + c4);
        uint4 u; u.x = f2tf32(v.x); u.y = f2tf32(v.y); u.z = f2tf32(v.z); u.w = f2tf32(v.w);
        *(uint4*)&AT_QS(r, c4) = u;
    }

    float m1 = -CUDART_INF_F, m2 = -CUDART_INF_F, l1 = 0.f, l2 = 0.f;
    float o[8][4];
    #pragma unroll
    for (int nt = 0; nt < 8; nt++)
        #pragma unroll
        for (int e = 0; e < 4; e++) o[nt][e] = 0.f;

    int cnt = 0;
    for (int ti = sp; ti < KTILES; ti += NSPLIT, cnt++) {
        int nxt = ti + NSPLIT;
        if (nxt < KTILES) { prefetch_kv((cnt + 1) & 1, nxt); CP_COMMIT(); CP_WAIT1(); }
        else              { CP_WAIT0(); }
        __syncthreads();
        const int b = cnt & 1;

        float sc[8][4];
        #pragma unroll
        for (int nt = 0; nt < 8; nt++)
            #pragma unroll
            for (int e = 0; e < 4; e++) sc[nt][e] = 0.f;
        #pragma unroll
        for (int ks8 = 0; ks8 < 8; ks8++) {
            const int k8 = ks8 * 8;
            uint32_t af[4];
            af[0] = AT_QS(m0 + g,     k8 + t);
            af[1] = AT_QS(m0 + g + 8, k8 + t);
            af[2] = AT_QS(m0 + g,     k8 + t + 4);
            af[3] = AT_QS(m0 + g + 8, k8 + t + 4);
            #pragma unroll
            for (int nt = 0; nt < 8; nt++) {
                uint32_t bf[2];
                bf[0] = AT_KS(b, nt * 8 + g, k8 + t);
                bf[1] = AT_KS(b, nt * 8 + g, k8 + t + 4);
                mma_tf32(sc[nt], af, bf);
            }
        }
        float mx1 = -CUDART_INF_F, mx2 = -CUDART_INF_F;
        #pragma unroll
        for (int nt = 0; nt < 8; nt++) {
            sc[nt][0] *= 0.125f; sc[nt][1] *= 0.125f;
            sc[nt][2] *= 0.125f; sc[nt][3] *= 0.125f;
            mx1 = fmaxf(mx1, fmaxf(sc[nt][0], sc[nt][1]));
            mx2 = fmaxf(mx2, fmaxf(sc[nt][2], sc[nt][3]));
        }
        #pragma unroll
        for (int off = 1; off <= 2; off <<= 1) {
            mx1 = fmaxf(mx1, __shfl_xor_sync(~0u, mx1, off));
            mx2 = fmaxf(mx2, __shfl_xor_sync(~0u, mx2, off));
        }
        float mn1 = fmaxf(m1, mx1), mn2 = fmaxf(m2, mx2);
        float fac1 = __expf(m1 - mn1), fac2 = __expf(m2 - mn2);
        float s1 = 0.f, s2 = 0.f;
        #pragma unroll
        for (int nt = 0; nt < 8; nt++) {
            sc[nt][0] = __expf(sc[nt][0] - mn1);
            sc[nt][1] = __expf(sc[nt][1] - mn1);
            sc[nt][2] = __expf(sc[nt][2] - mn2);
            sc[nt][3] = __expf(sc[nt][3] - mn2);
            s1 += sc[nt][0] + sc[nt][1];
            s2 += sc[nt][2] + sc[nt][3];
        }
        #pragma unroll
        for (int off = 1; off <= 2; off <<= 1) {
            s1 += __shfl_xor_sync(~0u, s1, off);
            s2 += __shfl_xor_sync(~0u, s2, off);
        }
        l1 = l1 * fac1 + s1; m1 = mn1;
        l2 = l2 * fac2 + s2; m2 = mn2;
        #pragma unroll
        for (int nt = 0; nt < 8; nt++) {
            o[nt][0] *= fac1; o[nt][1] *= fac1;
            o[nt][2] *= fac2; o[nt][3] *= fac2;
        }
        #pragma unroll
        for (int nt = 0; nt < 8; nt++) {
            AT_PS(warp, g,     nt * 8 + 2 * t)     = f2tf32(sc[nt][0]);
            AT_PS(warp, g,     nt * 8 + 2 * t + 1) = f2tf32(sc[nt][1]);
            AT_PS(warp, g + 8, nt * 8 + 2 * t)     = f2tf32(sc[nt][2]);
            AT_PS(warp, g + 8, nt * 8 + 2 * t + 1) = f2tf32(sc[nt][3]);
        }
        __syncwarp();
        #pragma unroll
        for (int ks8 = 0; ks8 < 8; ks8++) {
            const int k8 = ks8 * 8;
            uint32_t af[4];
            af[0] = AT_PS(warp, g,     k8 + t);
            af[1] = AT_PS(warp, g + 8, k8 + t);
            af[2] = AT_PS(warp, g,     k8 + t + 4);
            af[3] = AT_PS(warp, g + 8, k8 + t + 4);
            #pragma unroll
            for (int nt = 0; nt < 8; nt++) {
                uint32_t bf[2];
                bf[0] = AT_VS(b, k8 + t,     nt * 8 + g);
                bf[1] = AT_VS(b, k8 + t + 4, nt * 8 + g);
                mma_tf32(o[nt], af, bf);
            }
        }
        __syncthreads();
    }

    const int base = (bt * HEADS + h) * NSPLIT + sp;
    const int r1 = m0 + g, r2 = m0 + g + 8;
    if (t == 0) {
        g_pm[base * NLTN + r1] = m1;  g_pl[base * NLTN + r1] = l1;
        g_pm[base * NLTN + r2] = m2;  g_pl[base * NLTN + r2] = l2;
    }
    float* p1 = g_po + ((size_t)base * NLTN + r1) * DHEAD + 2 * t;
    float* p2 = g_po + ((size_t)base * NLTN + r2) * DHEAD + 2 * t;
    #pragma unroll
    for (int nt = 0; nt < 8; nt++) {
        *(float2*)(p1 + nt * 8) = make_float2(o[nt][0], o[nt][1]);
        *(float2*)(p2 + nt * 8) = make_float2(o[nt][2], o[nt][3]);
    }
}

// ---------------- combine partials -> tf32 attn out ----------------
__global__ void __launch_bounds__(256) attn_combine() {
    int bh = blockIdx.x;
    int bt = bh / HEADS, h = bh % HEADS;
    __shared__ float ws[NLTN][NSPLIT];
    __shared__ float linv[NLTN];
    int tid = threadIdx.x;
    if (tid < NLTN) {
        int row = tid;
        float m = -CUDART_INF_F;
        #pragma unroll
        for (int s = 0; s < NSPLIT; s++)
            m = fmaxf(m, g_pm[(bh * NSPLIT + s) * NLTN + row]);
        float L = 0.f;
        #pragma unroll
        for (int s = 0; s < NSPLIT; s++) {
            float w = __expf(g_pm[(bh * NSPLIT + s) * NLTN + row] - m);
            ws[row][s] = w;
            L += g_pl[(bh * NSPLIT + s) * NLTN + row] * w;
        }
        linv[row] = 1.f / L;
    }
    __syncthreads();
    for (int i = tid; i < NLTN * DHEAD; i += 256) {
        int row = i >> 6, d = i & 63;
        float acc = 0.f;
        #pragma unroll
        for (int s = 0; s < NSPLIT; s++)
            acc += g_po[(((size_t)bh * NSPLIT + s) * NLTN + row) * DHEAD + d] * ws[row][s];
        g_attn_t[((size_t)bt * NLTN + row) * DEMB + h * DHEAD + d] = f2tf32(acc * linv[row]);
    }
}

extern "C" void kernel_launch(void* const* d_in, const int* in_sizes, int n_in,
                              void* d_out, int out_size) {
    const float* src   = (const float*)d_in[0];
    const float* ltn   = (const float*)d_in[1];
    const float* gsrc  = (const float*)d_in[2];
    const float* bsrc  = (const float*)d_in[3];
    const float* gltn  = (const float*)d_in[4];
    const float* bltn  = (const float*)d_in[5];
    const float* Wq    = (const float*)d_in[6];
    const float* Wkv   = (const float*)d_in[7];
    const float* Wo    = (const float*)d_in[8];
    float* out = (float*)d_out;

    float *p_q, *p_kv;
    uint32_t *p_ltn_t, *p_srcn, *p_wkvt, *p_wqt, *p_wot, *p_attn_t;
    cudaGetSymbolAddress((void**)&p_q,      g_q);
    cudaGetSymbolAddress((void**)&p_kv,     g_kv);
    cudaGetSymbolAddress((void**)&p_ltn_t,  g_ltn_t);
    cudaGetSymbolAddress((void**)&p_srcn,   g_srcn);
    cudaGetSymbolAddress((void**)&p_wkvt,   g_wkvt);
    cudaGetSymbolAddress((void**)&p_wqt,    g_wqt);
    cudaGetSymbolAddress((void**)&p_wot,    g_wot);
    cudaGetSymbolAddress((void**)&p_attn_t, g_attn_t);

    cudaFuncSetAttribute(kv_src_mm, cudaFuncAttributeMaxDynamicSharedMemorySize, KVS_SMEM_BYTES);
    cudaFuncSetAttribute(attn_mma,  cudaFuncAttributeMaxDynamicSharedMemorySize, AT_SMEM_BYTES);

    // 1) preprocessing: LN(ltn)->tf32, normalized-tf32 src, tf32 weights
    ln_ltn_kernel<<<BT * NLTN, 256>>>(ltn, gltn, bltn);
    norm_src_tf32<<<BT * NSRC / 8, 256>>>(src, gsrc, bsrc);
    cvt_tf32<<<(DIM * 2 * DEMB) / 1024, 256>>>(Wkv, p_wkvt);
    cvt_tf32<<<(DIM * DEMB) / 1024, 256>>>(Wq, p_wqt);
    cvt_tf32<<<(DEMB * DIM) / 1024, 256>>>(Wo, p_wot);

    // 2) q = ltn_n @ Wq (tf32, 64 blocks)
    gemm64_tf32<false><<<dim3(DEMB / 64, (BT * NLTN) / 64), 128>>>(
        p_ltn_t, p_wqt, p_q, DIM, DEMB, BT * NLTN, 0, 0);

    // 3) kv (src rows): pure tf32 GEMM, async pipelined
    kv_src_mm<<<dim3(1024 / 128, (BT * NSRC) / 128), 256, KVS_SMEM_BYTES>>>(
        p_srcn, p_wkvt, p_kv);

    // 4) kv (ltn rows): tf32, appended at row 8192 of each bt chunk (128 blocks)
    gemm64_tf32<true><<<dim3(1024 / 64, (BT * NLTN) / 64), 128>>>(
        p_ltn_t, p_wkvt, p_kv, DIM, 2 * DEMB, NLTN, NSRC, NCTX);

    // 5) attention: tf32 mma split-KV + combine
    attn_mma<<<dim3(NSPLIT, HEADS, BT), 128, AT_SMEM_BYTES>>>(p_q, (const uint32_t*)p_kv);
    attn_combine<<<BT * HEADS, 256>>>();

    // 6) out = attn_out @ Wo (tf32, 96 blocks)
    gemm64_tf32<false><<<dim3(DIM / 64, (BT * NLTN) / 64), 128>>>(
        p_attn_t, p_wot, out, DEMB, DIM, BT * NLTN, 0, 0);
}

// round 9
// speedup vs baseline: 4.0750x; 1.0074x over previous
#include <cuda_runtime.h>
#include <math_constants.h>
#include <cstdint>

#define BT     8        // b*t
#define NSRC   8192
#define NLTN   64
#define NCTX   8256     // NSRC + NLTN
#define DIM    768
#define DEMB   512
#define HEADS  8
#define DHEAD  64
#define NSPLIT 32
#define KTILES 129      // NCTX / 64
#define EPS    1e-5f

// ---- scratch (device globals: no allocation allowed) ----
__device__ uint32_t g_ltn_t[BT * NLTN * DIM];         // LN(ltn) as tf32
__device__ float    g_q[BT * NLTN * DEMB];            // q as tf32 bits
__device__ float    g_kv[BT * NCTX * 2 * DEMB];       // 270 MB, tf32 bits
__device__ uint32_t g_srcn[BT * NSRC * DIM];          // normalized src (tf32)
__device__ uint32_t g_wkvt[DIM * 2 * DEMB];
__device__ uint32_t g_wqt[DIM * DEMB];
__device__ uint32_t g_wot[DEMB * DIM];
__device__ uint32_t g_attn_t[BT * NLTN * DEMB];
__device__ float    g_po[BT * HEADS * NSPLIT * NLTN * DHEAD];
__device__ float    g_pm[BT * HEADS * NSPLIT * NLTN];
__device__ float    g_pl[BT * HEADS * NSPLIT * NLTN];

// ---------------- helpers ----------------
__device__ __forceinline__ uint32_t f2tf32(float f) {
    uint32_t u;
    asm("cvt.rna.tf32.f32 %0, %1;" : "=r"(u) : "f"(f));
    return u;
}
__device__ __forceinline__ void mma_tf32(float* d, const uint32_t* a, const uint32_t* b) {
    asm volatile(
        "mma.sync.aligned.m16n8k8.row.col.f32.tf32.tf32.f32 "
        "{%0,%1,%2,%3}, {%4,%5,%6,%7}, {%8,%9}, {%0,%1,%2,%3};\n"
        : "+f"(d[0]), "+f"(d[1]), "+f"(d[2]), "+f"(d[3])
        : "r"(a[0]), "r"(a[1]), "r"(a[2]), "r"(a[3]), "r"(b[0]), "r"(b[1]));
}
__device__ __forceinline__ void cp16(void* dst_smem, const void* src) {
    uint32_t d = (uint32_t)__cvta_generic_to_shared(dst_smem);
    asm volatile("cp.async.cg.shared.global [%0], [%1], 16;" :: "r"(d), "l"(src));
}
#define CP_COMMIT() asm volatile("cp.async.commit_group;")
#define CP_WAIT0()  asm volatile("cp.async.wait_group 0;")
#define CP_WAIT1()  asm volatile("cp.async.wait_group 1;")
#define CP_WAIT2()  asm volatile("cp.async.wait_group 2;")

// ---------------- LayerNorm of ltn -> tf32 (512 rows) ----------------
__global__ void ln_ltn_kernel(const float* __restrict__ ltn,
                              const float* __restrict__ g,
                              const float* __restrict__ b) {
    int row = blockIdx.x;
    const float* x = ltn + (size_t)row * DIM;
    int tid = threadIdx.x;
    float v0 = x[tid], v1 = x[tid + 256], v2 = x[tid + 512];
    float s  = v0 + v1 + v2;
    float s2 = v0 * v0 + v1 * v1 + v2 * v2;
    __shared__ float red[2][8];
    #pragma unroll
    for (int o = 16; o; o >>= 1) {
        s  += __shfl_xor_sync(~0u, s,  o);
        s2 += __shfl_xor_sync(~0u, s2, o);
    }
    int w = tid >> 5, l = tid & 31;
    if (l == 0) { red[0][w] = s; red[1][w] = s2; }
    __syncthreads();
    s = 0.f; s2 = 0.f;
    #pragma unroll
    for (int i = 0; i < 8; i++) { s += red[0][i]; s2 += red[1][i]; }
    float mean = s * (1.f / DIM);
    float var  = s2 * (1.f / DIM) - mean * mean;
    float rstd = rsqrtf(var + EPS);
    uint32_t* out = g_ltn_t + (size_t)row * DIM;
    out[tid]       = f2tf32((v0 - mean) * rstd * g[tid]       + b[tid]);
    out[tid + 256] = f2tf32((v1 - mean) * rstd * g[tid + 256] + b[tid + 256]);
    out[tid + 512] = f2tf32((v2 - mean) * rstd * g[tid + 512] + b[tid + 512]);
}

// ---------------- normalize src -> tf32 ----------------
__global__ void __launch_bounds__(256)
norm_src_tf32(const float* __restrict__ src,
              const float* __restrict__ g, const float* __restrict__ b) {
    int w = threadIdx.x >> 5, l = threadIdx.x & 31;
    int row = blockIdx.x * 8 + w;
    const float* x = src + (size_t)row * DIM;
    float4 v[6];
    float s = 0.f, s2 = 0.f;
    #pragma unroll
    for (int i = 0; i < 6; i++) {
        v[i] = *(const float4*)(x + i * 128 + l * 4);
        s  += v[i].x + v[i].y + v[i].z + v[i].w;
        s2 += v[i].x * v[i].x + v[i].y * v[i].y + v[i].z * v[i].z + v[i].w * v[i].w;
    }
    #pragma unroll
    for (int o = 16; o; o >>= 1) {
        s  += __shfl_xor_sync(~0u, s,  o);
        s2 += __shfl_xor_sync(~0u, s2, o);
    }
    float mean = s * (1.f / DIM);
    float var  = s2 * (1.f / DIM) - mean * mean;
    float rstd = rsqrtf(var + EPS);
    uint32_t* o = g_srcn + (size_t)row * DIM;
    #pragma unroll
    for (int i = 0; i < 6; i++) {
        int c = i * 128 + l * 4;
        float4 gg = *(const float4*)(g + c);
        float4 bb = *(const float4*)(b + c);
        uint4 u;
        u.x = f2tf32((v[i].x - mean) * rstd * gg.x + bb.x);
        u.y = f2tf32((v[i].y - mean) * rstd * gg.y + bb.y);
        u.z = f2tf32((v[i].z - mean) * rstd * gg.z + bb.z);
        u.w = f2tf32((v[i].w - mean) * rstd * gg.w + bb.w);
        *(uint4*)(o + c) = u;
    }
}

// ---------------- convert fp32 weights to tf32 ----------------
__global__ void cvt_tf32(const float* __restrict__ in, uint32_t* __restrict__ out) {
    int i = (blockIdx.x * 256 + threadIdx.x) * 4;
    float4 v = *(const float4*)(in + i);
    uint4 u;
    u.x = f2tf32(v.x); u.y = f2tf32(v.y); u.z = f2tf32(v.z); u.w = f2tf32(v.w);
    *(uint4*)(out + i) = u;
}

// ---------------- KV projection (src rows): tf32, cp.async 3-stage ----------------
#define KVS_STAGE_A 4608                // 128*36
#define KVS_STAGE   8960                // + 32*136
#define KVS_A(s,r,c) dynu[(s) * KVS_STAGE + (r) * 36 + (c)]
#define KVS_B(s,r,c) dynu[(s) * KVS_STAGE + KVS_STAGE_A + (r) * 136 + (c)]
#define KVS_SMEM_BYTES (3 * KVS_STAGE * 4)
#define NCHUNK 24

__global__ void __launch_bounds__(256, 2)
kv_src_mm(const uint32_t* __restrict__ A, const uint32_t* __restrict__ W,
          float* __restrict__ C) {
    extern __shared__ uint32_t dynu[];
    const int tid = threadIdx.x;
    const int lane = tid & 31, warp = tid >> 5;
    const int row0 = blockIdx.y * 128, col0 = blockIdx.x * 128;
    const int N = 2 * DEMB;

    const int wm = warp & 3, wn = warp >> 2;
    const int m0w = wm * 32, n0w = wn * 64;
    const int g = lane >> 2, t = lane & 3;

    float acc[2][8][4];
    #pragma unroll
    for (int mt = 0; mt < 2; mt++)
        #pragma unroll
        for (int nt = 0; nt < 8; nt++)
            #pragma unroll
            for (int e = 0; e < 4; e++) acc[mt][nt][e] = 0.f;

    auto prefetch = [&](int buf, int c) {
        int k0 = c * 32;
        #pragma unroll
        for (int i = 0; i < 4; i++) {
            int slot = tid + i * 256;
            int r = slot >> 3, c4 = (slot & 7) * 4;
            cp16(&KVS_A(buf, r, c4), A + (size_t)(row0 + r) * DIM + k0 + c4);
        }
        #pragma unroll
        for (int i = 0; i < 4; i++) {
            int slot = tid + i * 256;
            int r = slot >> 5, c4 = (slot & 31) * 4;
            cp16(&KVS_B(buf, r, c4), W + (size_t)(k0 + r) * N + col0 + c4);
        }
    };

    prefetch(0, 0); CP_COMMIT();
    prefetch(1, 1); CP_COMMIT();

    for (int c = 0; c < NCHUNK; c++) {
        if (c < NCHUNK - 1) CP_WAIT1(); else CP_WAIT0();
        __syncthreads();                       // stage c visible; all done with stage (c-1)%3
        if (c + 2 < NCHUNK) { prefetch((c + 2) % 3, c + 2); CP_COMMIT(); }

        const int b = c % 3;
        #pragma unroll
        for (int ks8 = 0; ks8 < 4; ks8++) {
            const int k8 = ks8 * 8;
            uint32_t af[2][4];
            #pragma unroll
            for (int mt = 0; mt < 2; mt++) {
                int r = m0w + mt * 16 + g;
                af[mt][0] = KVS_A(b, r,     k8 + t);
                af[mt][1] = KVS_A(b, r + 8, k8 + t);
                af[mt][2] = KVS_A(b, r,     k8 + t + 4);
                af[mt][3] = KVS_A(b, r + 8, k8 + t + 4);
            }
            #pragma unroll
            for (int nt = 0; nt < 8; nt++) {
                uint32_t bf[2];
                int cc = n0w + nt * 8 + g;
                bf[0] = KVS_B(b, k8 + t,     cc);
                bf[1] = KVS_B(b, k8 + 4 + t, cc);
                mma_tf32(acc[0][nt], af[0], bf);
                mma_tf32(acc[1][nt], af[1], bf);
            }
        }
    }

    const int bt  = row0 / NSRC;
    const int rin = row0 % NSRC;
    const size_t crow0 = (size_t)bt * NCTX + rin;
    #pragma unroll
    for (int mt = 0; mt < 2; mt++) {
        int r = m0w + mt * 16 + g;
        float* c0 = C + (crow0 + r) * (size_t)N + col0 + n0w + 2 * t;
        float* c1 = c0 + 8 * (size_t)N;
        #pragma unroll
        for (int nt = 0; nt < 8; nt++) {
            *(float2*)(c0 + nt * 8) = make_float2(__uint_as_float(f2tf32(acc[mt][nt][0])),
                                                  __uint_as_float(f2tf32(acc[mt][nt][1])));
            *(float2*)(c1 + nt * 8) = make_float2(__uint_as_float(f2tf32(acc[mt][nt][2])),
                                                  __uint_as_float(f2tf32(acc[mt][nt][3])));
        }
    }
}

// ---------------- small tf32 GEMM: 64x64 tiles, 4 warps, cp.async 2-stage ----------------
template <bool OUT_TF32>
__global__ void __launch_bounds__(128)
gemm64_tf32(const uint32_t* __restrict__ A, const uint32_t* __restrict__ W,
            float* __restrict__ C,
            int K, int N, int rows_per_bt, int out_off, int out_stride) {
    __shared__ uint32_t As[2][64][36];
    __shared__ uint32_t Bs[2][32][72];

    const int tid = threadIdx.x;
    const int lane = tid & 31, warp = tid >> 5;
    const int row0 = blockIdx.y * 64, col0 = blockIdx.x * 64;
    const int wm = warp & 1, wn = warp >> 1;
    const int m0w = wm * 32, n0w = wn * 32;
    const int g = lane >> 2, t = lane & 3;

    float acc[2][4][4];
    #pragma unroll
    for (int mt = 0; mt < 2; mt++)
        #pragma unroll
        for (int nt = 0; nt < 4; nt++)
            #pragma unroll
            for (int e = 0; e < 4; e++) acc[mt][nt][e] = 0.f;

    auto prefetch = [&](int buf, int c) {
        int k0 = c * 32;
        #pragma unroll
        for (int i = 0; i < 4; i++) {
            int slot = tid + i * 128;
            int r = slot >> 3, c4 = (slot & 7) * 4;
            cp16(&As[buf][r][c4], A + (size_t)(row0 + r) * K + k0 + c4);
        }
        #pragma unroll
        for (int i = 0; i < 4; i++) {
            int slot = tid + i * 128;
            int r = slot >> 4, c4 = (slot & 15) * 4;
            cp16(&Bs[buf][r][c4], W + (size_t)(k0 + r) * N + col0 + c4);
        }
    };

    const int NC = K / 32;
    prefetch(0, 0);
    CP_COMMIT();

    for (int c = 0; c < NC; c++) {
        if (c < NC - 1) { prefetch((c + 1) & 1, c + 1); CP_COMMIT(); CP_WAIT1(); }
        else            { CP_WAIT0(); }
        __syncthreads();

        const int b = c & 1;
        #pragma unroll
        for (int ks8 = 0; ks8 < 4; ks8++) {
            const int k8 = ks8 * 8;
            uint32_t af[2][4];
            #pragma unroll
            for (int mt = 0; mt < 2; mt++) {
                int r = m0w + mt * 16 + g;
                af[mt][0] = As[b][r][k8 + t];
                af[mt][1] = As[b][r + 8][k8 + t];
                af[mt][2] = As[b][r][k8 + t + 4];
                af[mt][3] = As[b][r + 8][k8 + t + 4];
            }
            #pragma unroll
            for (int nt = 0; nt < 4; nt++) {
                uint32_t bf[2];
                int cc = n0w + nt * 8 + g;
                bf[0] = Bs[b][k8 + t][cc];
                bf[1] = Bs[b][k8 + 4 + t][cc];
                mma_tf32(acc[0][nt], af[0], bf);
                mma_tf32(acc[1][nt], af[1], bf);
            }
        }
        __syncthreads();
    }

    #pragma unroll
    for (int mt = 0; mt < 2; mt++) {
        int grow = row0 + m0w + mt * 16 + g;
        int bt = grow / rows_per_bt;
        int r  = grow % rows_per_bt;
        size_t crow  = (size_t)bt * out_stride + out_off + r;
        int grow2 = grow + 8;
        int bt2 = grow2 / rows_per_bt;
        int r2  = grow2 % rows_per_bt;
        size_t crow2 = (size_t)bt2 * out_stride + out_off + r2;
        float* c0 = C + crow  * N + col0 + n0w + 2 * t;
        float* c1 = C + crow2 * N + col0 + n0w + 2 * t;
        #pragma unroll
        for (int nt = 0; nt < 4; nt++) {
            if (OUT_TF32) {
                *(float2*)(c0 + nt * 8) = make_float2(__uint_as_float(f2tf32(acc[mt][nt][0])),
                                                      __uint_as_float(f2tf32(acc[mt][nt][1])));
                *(float2*)(c1 + nt * 8) = make_float2(__uint_as_float(f2tf32(acc[mt][nt][2])),
                                                      __uint_as_float(f2tf32(acc[mt][nt][3])));
            } else {
                *(float2*)(c0 + nt * 8) = make_float2(acc[mt][nt][0], acc[mt][nt][1]);
                *(float2*)(c1 + nt * 8) = make_float2(acc[mt][nt][2], acc[mt][nt][3]);
            }
        }
    }
}

// ---------------- attention partial: tf32 mma, q in regs, K dbuf, V sbuf ----------------
// smem words: KS[2][64][68] @0, VS[64][72] @8704, PS[4][16][68] @13312  (total 17664 = 70.7KB)
#define AT_KS(b,r,c)  dynu[(b) * 4352 + (r) * 68 + (c)]
#define AT_VS(r,c)    dynu[8704 + (r) * 72 + (c)]
#define AT_PS(w,r,c)  dynu[13312 + (w) * 1088 + (r) * 68 + (c)]
#define AT_QT(r,c)    dynu[13312 + (r) * 68 + (c)]      // q staging reuses PS area
#define AT_SMEM_BYTES (17664 * 4)

__global__ void __launch_bounds__(128, 3)
attn_mma(const uint32_t* __restrict__ q, const uint32_t* __restrict__ kvp) {
    extern __shared__ uint32_t dynu[];
    const int sp = blockIdx.x, h = blockIdx.y, bt = blockIdx.z;
    const int tid = threadIdx.x, lane = tid & 31, warp = tid >> 5;
    const int g = lane >> 2, t = lane & 3;
    const int m0 = warp * 16;
    const uint32_t* kvbase = kvp + (size_t)bt * NCTX * (2 * DEMB) + h * DHEAD;

    auto prefetch_K = [&](int buf, int ti) {
        int j0 = ti * 64;
        #pragma unroll
        for (int i = 0; i < 8; i++) {
            int slot = tid + i * 128;
            int key = slot >> 4, c4 = (slot & 15) * 4;
            cp16(&AT_KS(buf, key, c4), kvbase + (size_t)(j0 + key) * (2 * DEMB) + c4);
        }
    };
    auto prefetch_V = [&](int ti) {
        int j0 = ti * 64;
        #pragma unroll
        for (int i = 0; i < 8; i++) {
            int slot = tid + i * 128;
            int key = slot >> 4, c4 = (slot & 15) * 4;
            cp16(&AT_VS(key, c4), kvbase + (size_t)(j0 + key) * (2 * DEMB) + DEMB + c4);
        }
    };

    // q -> PS area (async), then K0, V0
    #pragma unroll
    for (int i = 0; i < 8; i++) {
        int slot = tid + i * 128;
        int r = slot >> 4, c4 = (slot & 15) * 4;
        cp16(&AT_QT(r, c4), q + ((size_t)bt * NLTN + r) * DEMB + h * DHEAD + c4);
    }
    CP_COMMIT();
    prefetch_K(0, sp); CP_COMMIT();
    prefetch_V(sp);    CP_COMMIT();

    CP_WAIT2();            // q ready
    __syncthreads();
    uint32_t qf[8][4];
    #pragma unroll
    for (int ks8 = 0; ks8 < 8; ks8++) {
        const int k8 = ks8 * 8;
        qf[ks8][0] = AT_QT(m0 + g,     k8 + t);
        qf[ks8][1] = AT_QT(m0 + g + 8, k8 + t);
        qf[ks8][2] = AT_QT(m0 + g,     k8 + t + 4);
        qf[ks8][3] = AT_QT(m0 + g + 8, k8 + t + 4);
    }

    float m1 = -CUDART_INF_F, m2 = -CUDART_INF_F, l1 = 0.f, l2 = 0.f;
    float o[8][4];
    #pragma unroll
    for (int nt = 0; nt < 8; nt++)
        #pragma unroll
        for (int e = 0; e < 4; e++) o[nt][e] = 0.f;

    int cnt = 0;
    for (int ti = sp; ti < KTILES; ti += NSPLIT, cnt++) {
        const int nxt = ti + NSPLIT;
        const bool hasnext = nxt < KTILES;
        if (hasnext) { prefetch_K((cnt + 1) & 1, nxt); CP_COMMIT(); }
        if (hasnext) CP_WAIT2(); else CP_WAIT1();    // K_i ready
        __syncthreads();                             // (also: qf reads done / PS free)
        const int b = cnt & 1;

        // scores
        float sc[8][4];
        #pragma unroll
        for (int nt = 0; nt < 8; nt++)
            #pragma unroll
            for (int e = 0; e < 4; e++) sc[nt][e] = 0.f;
        #pragma unroll
        for (int ks8 = 0; ks8 < 8; ks8++) {
            const int k8 = ks8 * 8;
            #pragma unroll
            for (int nt = 0; nt < 8; nt++) {
                uint32_t bf[2];
                bf[0] = AT_KS(b, nt * 8 + g, k8 + t);
                bf[1] = AT_KS(b, nt * 8 + g, k8 + t + 4);
                mma_tf32(sc[nt], qf[ks8], bf);
            }
        }
        // online softmax (rows g, g+8)
        float mx1 = -CUDART_INF_F, mx2 = -CUDART_INF_F;
        #pragma unroll
        for (int nt = 0; nt < 8; nt++) {
            sc[nt][0] *= 0.125f; sc[nt][1] *= 0.125f;
            sc[nt][2] *= 0.125f; sc[nt][3] *= 0.125f;
            mx1 = fmaxf(mx1, fmaxf(sc[nt][0], sc[nt][1]));
            mx2 = fmaxf(mx2, fmaxf(sc[nt][2], sc[nt][3]));
        }
        #pragma unroll
        for (int off = 1; off <= 2; off <<= 1) {
            mx1 = fmaxf(mx1, __shfl_xor_sync(~0u, mx1, off));
            mx2 = fmaxf(mx2, __shfl_xor_sync(~0u, mx2, off));
        }
        float mn1 = fmaxf(m1, mx1), mn2 = fmaxf(m2, mx2);
        float fac1 = __expf(m1 - mn1), fac2 = __expf(m2 - mn2);
        float s1 = 0.f, s2 = 0.f;
        #pragma unroll
        for (int nt = 0; nt < 8; nt++) {
            sc[nt][0] = __expf(sc[nt][0] - mn1);
            sc[nt][1] = __expf(sc[nt][1] - mn1);
            sc[nt][2] = __expf(sc[nt][2] - mn2);
            sc[nt][3] = __expf(sc[nt][3] - mn2);
            s1 += sc[nt][0] + sc[nt][1];
            s2 += sc[nt][2] + sc[nt][3];
        }
        #pragma unroll
        for (int off = 1; off <= 2; off <<= 1) {
            s1 += __shfl_xor_sync(~0u, s1, off);
            s2 += __shfl_xor_sync(~0u, s2, off);
        }
        l1 = l1 * fac1 + s1; m1 = mn1;
        l2 = l2 * fac2 + s2; m2 = mn2;
        #pragma unroll
        for (int nt = 0; nt < 8; nt++) {
            o[nt][0] *= fac1; o[nt][1] *= fac1;
            o[nt][2] *= fac2; o[nt][3] *= fac2;
        }
        // p -> per-warp slab (tf32)
        #pragma unroll
        for (int nt = 0; nt < 8; nt++) {
            AT_PS(warp, g,     nt * 8 + 2 * t)     = f2tf32(sc[nt][0]);
            AT_PS(warp, g,     nt * 8 + 2 * t + 1) = f2tf32(sc[nt][1]);
            AT_PS(warp, g + 8, nt * 8 + 2 * t)     = f2tf32(sc[nt][2]);
            AT_PS(warp, g + 8, nt * 8 + 2 * t + 1) = f2tf32(sc[nt][3]);
        }
        __syncwarp();
        if (hasnext) CP_WAIT1(); else CP_WAIT0();    // V_i ready
        __syncthreads();
        // o += p @ v
        #pragma unroll
        for (int ks8 = 0; ks8 < 8; ks8++) {
            const int k8 = ks8 * 8;
            uint32_t af[4];
            af[0] = AT_PS(warp, g,     k8 + t);
            af[1] = AT_PS(warp, g + 8, k8 + t);
            af[2] = AT_PS(warp, g,     k8 + t + 4);
            af[3] = AT_PS(warp, g + 8, k8 + t + 4);
            #pragma unroll
            for (int nt = 0; nt < 8; nt++) {
                uint32_t bf[2];
                bf[0] = AT_VS(k8 + t,     nt * 8 + g);
                bf[1] = AT_VS(k8 + t + 4, nt * 8 + g);
                mma_tf32(o[nt], af, bf);
            }
        }
        __syncthreads();                             // all warps done with V buffer
        if (hasnext) { prefetch_V(nxt); CP_COMMIT(); }
    }

    const int base = (bt * HEADS + h) * NSPLIT + sp;
    const int r1 = m0 + g, r2 = m0 + g + 8;
    if (t == 0) {
        g_pm[base * NLTN + r1] = m1;  g_pl[base * NLTN + r1] = l1;
        g_pm[base * NLTN + r2] = m2;  g_pl[base * NLTN + r2] = l2;
    }
    float* p1 = g_po + ((size_t)base * NLTN + r1) * DHEAD + 2 * t;
    float* p2 = g_po + ((size_t)base * NLTN + r2) * DHEAD + 2 * t;
    #pragma unroll
    for (int nt = 0; nt < 8; nt++) {
        *(float2*)(p1 + nt * 8) = make_float2(o[nt][0], o[nt][1]);
        *(float2*)(p2 + nt * 8) = make_float2(o[nt][2], o[nt][3]);
    }
}

// ---------------- combine partials -> tf32 attn out ----------------
__global__ void __launch_bounds__(256) attn_combine() {
    int bh = blockIdx.x;
    int bt = bh / HEADS, h = bh % HEADS;
    __shared__ float ws[NLTN][NSPLIT];
    __shared__ float linv[NLTN];
    int tid = threadIdx.x;
    if (tid < NLTN) {
        int row = tid;
        float m = -CUDART_INF_F;
        #pragma unroll
        for (int s = 0; s < NSPLIT; s++)
            m = fmaxf(m, g_pm[(bh * NSPLIT + s) * NLTN + row]);
        float L = 0.f;
        #pragma unroll
        for (int s = 0; s < NSPLIT; s++) {
            float w = __expf(g_pm[(bh * NSPLIT + s) * NLTN + row] - m);
            ws[row][s] = w;
            L += g_pl[(bh * NSPLIT + s) * NLTN + row] * w;
        }
        linv[row] = 1.f / L;
    }
    __syncthreads();
    for (int i = tid; i < NLTN * DHEAD; i += 256) {
        int row = i >> 6, d = i & 63;
        float acc = 0.f;
        #pragma unroll
        for (int s = 0; s < NSPLIT; s++)
            acc += g_po[(((size_t)bh * NSPLIT + s) * NLTN + row) * DHEAD + d] * ws[row][s];
        g_attn_t[((size_t)bt * NLTN + row) * DEMB + h * DHEAD + d] = f2tf32(acc * linv[row]);
    }
}

extern "C" void kernel_launch(void* const* d_in, const int* in_sizes, int n_in,
                              void* d_out, int out_size) {
    const float* src   = (const float*)d_in[0];
    const float* ltn   = (const float*)d_in[1];
    const float* gsrc  = (const float*)d_in[2];
    const float* bsrc  = (const float*)d_in[3];
    const float* gltn  = (const float*)d_in[4];
    const float* bltn  = (const float*)d_in[5];
    const float* Wq    = (const float*)d_in[6];
    const float* Wkv   = (const float*)d_in[7];
    const float* Wo    = (const float*)d_in[8];
    float* out = (float*)d_out;

    float *p_q, *p_kv;
    uint32_t *p_ltn_t, *p_srcn, *p_wkvt, *p_wqt, *p_wot, *p_attn_t;
    cudaGetSymbolAddress((void**)&p_q,      g_q);
    cudaGetSymbolAddress((void**)&p_kv,     g_kv);
    cudaGetSymbolAddress((void**)&p_ltn_t,  g_ltn_t);
    cudaGetSymbolAddress((void**)&p_srcn,   g_srcn);
    cudaGetSymbolAddress((void**)&p_wkvt,   g_wkvt);
    cudaGetSymbolAddress((void**)&p_wqt,    g_wqt);
    cudaGetSymbolAddress((void**)&p_wot,    g_wot);
    cudaGetSymbolAddress((void**)&p_attn_t, g_attn_t);

    cudaFuncSetAttribute(kv_src_mm, cudaFuncAttributeMaxDynamicSharedMemorySize, KVS_SMEM_BYTES);
    cudaFuncSetAttribute(attn_mma,  cudaFuncAttributeMaxDynamicSharedMemorySize, AT_SMEM_BYTES);

    // 1) preprocessing
    ln_ltn_kernel<<<BT * NLTN, 256>>>(ltn, gltn, bltn);
    norm_src_tf32<<<BT * NSRC / 8, 256>>>(src, gsrc, bsrc);
    cvt_tf32<<<(DIM * 2 * DEMB) / 1024, 256>>>(Wkv, p_wkvt);
    cvt_tf32<<<(DIM * DEMB) / 1024, 256>>>(Wq, p_wqt);
    cvt_tf32<<<(DEMB * DIM) / 1024, 256>>>(Wo, p_wot);

    // 2) q = ltn_n @ Wq (tf32 output bits)
    gemm64_tf32<true><<<dim3(DEMB / 64, (BT * NLTN) / 64), 128>>>(
        p_ltn_t, p_wqt, p_q, DIM, DEMB, BT * NLTN, 0, 0);

    // 3) kv (src rows): tf32 GEMM, 3-stage pipeline
    kv_src_mm<<<dim3(1024 / 128, (BT * NSRC) / 128), 256, KVS_SMEM_BYTES>>>(
        p_srcn, p_wkvt, p_kv);

    // 4) kv (ltn rows)
    gemm64_tf32<true><<<dim3(1024 / 64, (BT * NLTN) / 64), 128>>>(
        p_ltn_t, p_wkvt, p_kv, DIM, 2 * DEMB, NLTN, NSRC, NCTX);

    // 5) attention + combine
    attn_mma<<<dim3(NSPLIT, HEADS, BT), 128, AT_SMEM_BYTES>>>(
        (const uint32_t*)p_q, (const uint32_t*)p_kv);
    attn_combine<<<BT * HEADS, 256>>>();

    // 6) out = attn_out @ Wo
    gemm64_tf32<false><<<dim3(DIM / 64, (BT * NLTN) / 64), 128>>>(
        p_attn_t, p_wot, out, DEMB, DIM, BT * NLTN, 0, 0);
}